// round 11
// baseline (speedup 1.0000x reference)
#include <cuda_runtime.h>
#include <cuda_fp16.h>
#include <math.h>
#include <stdint.h>

#define BATCH 2
#define SEQ   2048
#define EMB   1024
#define NHEAD 16
#define HDIM  64
#define MTOT  (BATCH*SEQ)   // 4096

// Scratch (allocation-free contract: __device__ globals)
__device__ float g_q[BATCH*NHEAD*SEQ*HDIM];   // [b][h][s][d]
__device__ float g_k[BATCH*NHEAD*SEQ*HDIM];
__device__ float g_v[BATCH*NHEAD*SEQ*HDIM];
__device__ float g_ctx[(size_t)MTOT*EMB];     // [b*s][e]

// ===========================================================================
// m16n8k16 fp16 mma.sync, fp32 accumulate (sm_80+ PTX; tcgen05 unreachable —
// harness builds compute_103 PTX). Calibrated: ~0.5 mma/cyc/SM ceiling.
// ===========================================================================
__device__ __forceinline__ void mma16(float* d, const uint32_t* a, const uint32_t* b) {
    asm volatile(
        "mma.sync.aligned.m16n8k16.row.col.f32.f16.f16.f32 "
        "{%0,%1,%2,%3}, {%4,%5,%6,%7}, {%8,%9}, {%0,%1,%2,%3};"
        : "+f"(d[0]), "+f"(d[1]), "+f"(d[2]), "+f"(d[3])
        : "r"(a[0]), "r"(a[1]), "r"(a[2]), "r"(a[3]), "r"(b[0]), "r"(b[1]));
}

// Split float4 into fp16 (hi, lo) pair-packed b32 words.
__device__ __forceinline__ uint4 split4(float4 g) {
    __half2 h01 = __floats2half2_rn(g.x, g.y);
    __half2 h23 = __floats2half2_rn(g.z, g.w);
    float2 f01 = __half22float2(h01);
    float2 f23 = __half22float2(h23);
    __half2 l01 = __floats2half2_rn(g.x - f01.x, g.y - f01.y);
    __half2 l23 = __floats2half2_rn(g.z - f23.x, g.w - f23.y);
    uint4 r;
    r.x = *reinterpret_cast<uint32_t*>(&h01);
    r.y = *reinterpret_cast<uint32_t*>(&l01);
    r.z = *reinterpret_cast<uint32_t*>(&h23);
    r.w = *reinterpret_cast<uint32_t*>(&l23);
    return r;
}

// Pack two fp32 into fp16 hi-pair + lo-pair b32 words (register-only).
__device__ __forceinline__ void pack_hl(float x, float y, uint32_t& h, uint32_t& l) {
    __half2 hh = __floats2half2_rn(x, y);
    float2 f = __half22float2(hh);
    __half2 ll = __floats2half2_rn(x - f.x, y - f.y);
    h = *reinterpret_cast<uint32_t*>(&hh);
    l = *reinterpret_cast<uint32_t*>(&ll);
}

// ===========================================================================
// 3xFP16 mma.sync GEMM, double-buffered, 2-CTA-PER-SM (R10 change):
// CTA tile 64x128, BK=32, 256 threads = 8 warps (2m x 4n grid of 32x32 warp
// tiles). Stage = A 8KB + B 16KB = 24KB, x2 = 48KB; regs ~106 -> two CTAs
// co-resident per SM. R9 profile showed nothing saturated (tensor 35%,
// issue 41%, L1 54%, occ 25%): latency/barrier bound at 1 CTA/SM. A second
// CTA fills those bubbles.
// Fragment-major smem, uint2 = (hi_pair, lo_pair); 3 passes hh/hl/lh.
// EPI==0: scatter to g_q/g_k/g_v.  EPI==1: A=g_ctx, out = C + bias.
// ===========================================================================
#define GEMM_STAGE_BYTES 24576
#define GEMM_SMEM_BYTES  (2*GEMM_STAGE_BYTES)   // 48 KB

template<int EPI>
__global__ __launch_bounds__(256, 2) void mma_gemm_kernel(
    const float* __restrict__ Ain,
    const float* __restrict__ W,
    const float* __restrict__ bias,
    float* __restrict__ out,
    int K, int Nfull)
{
    extern __shared__ char dsmem[];
    const float* A = (EPI == 1) ? (const float*)g_ctx : Ain;

    const int tid  = threadIdx.x;
    const int wid  = tid >> 5;
    const int lane = tid & 31;
    const int wm   = wid & 1;      // 2 row groups of 32
    const int wn   = wid >> 1;     // 4 col groups of 32
    const int gr   = lane >> 2;
    const int tg   = lane & 3;
    const int m0   = blockIdx.y * 64;
    const int n0   = blockIdx.x * 128;

    // ---- fill slots: A 2 float4/thread (64x32), B 4 float4/thread (128x32)
    const float *pA[2], *pB[4];
    int offA[2], offB[4];      // uint2 indices within a stage
    #pragma unroll
    for (int t = 0; t < 2; t++) {
        int idx = tid + t * 256;     // 0..511
        int row = idx >> 3;          // 0..63
        int c4  = idx & 7;
        pA[t] = A + (size_t)(m0 + row) * K + c4 * 4;
        int kk  = c4 >> 2;
        int kw4 = c4 & 3;
        int aih = kw4 >> 1;
        int tg0 = (kw4 & 1) * 2;
        int mt = row >> 4, rw = row & 15;
        int ai = (rw >> 3) | (aih << 1);
        offA[t] = (((kk*4 + mt)*4 + ai) << 5) + (rw & 7)*4 + tg0;
    }
    #pragma unroll
    for (int t = 0; t < 4; t++) {
        int idx = tid + t * 256;     // 0..1023
        int row = idx >> 3;          // 0..127
        int c4  = idx & 7;
        pB[t] = W + (size_t)(n0 + row) * K + c4 * 4;
        int kk  = c4 >> 2;
        int kw4 = c4 & 3;
        int bi  = kw4 >> 1;
        int tg0 = (kw4 & 1) * 2;
        int nt  = row >> 3;
        offB[t] = (((kk*16 + nt)*2 + bi) << 5) + (row & 7)*4 + tg0;
    }

    float acc[2][4][4];
    #pragma unroll
    for (int i = 0; i < 2; i++)
        #pragma unroll
        for (int j = 0; j < 4; j++)
            #pragma unroll
            for (int v = 0; v < 4; v++) acc[i][j][v] = 0.f;

    // ---- prologue: load + fill stage 0 ----
    float4 gA[2], gB[4];
    #pragma unroll
    for (int t = 0; t < 2; t++) gA[t] = *(const float4*)(pA[t]);
    #pragma unroll
    for (int t = 0; t < 4; t++) gB[t] = *(const float4*)(pB[t]);
    {
        uint2* sA0 = (uint2*)(dsmem);
        uint2* sB0 = (uint2*)(dsmem + 8192);
        #pragma unroll
        for (int t = 0; t < 2; t++) *(uint4*)(sA0 + offA[t]) = split4(gA[t]);
        #pragma unroll
        for (int t = 0; t < 4; t++) *(uint4*)(sB0 + offB[t]) = split4(gB[t]);
    }
    __syncthreads();

    const int niter = K >> 5;   // BK = 32
    for (int it = 0; it < niter; it++) {
        const int p = it & 1;
        uint2* cA = (uint2*)(dsmem + p*GEMM_STAGE_BYTES);
        uint2* cB = (uint2*)(dsmem + p*GEMM_STAGE_BYTES + 8192);
        const bool more = (it + 1 < niter);

        // prefetch next slab into registers (covered by the mma block)
        if (more) {
            const int ko = (it + 1) << 5;
            #pragma unroll
            for (int t = 0; t < 2; t++) gA[t] = *(const float4*)(pA[t] + ko);
            #pragma unroll
            for (int t = 0; t < 4; t++) gB[t] = *(const float4*)(pB[t] + ko);
        }

        // ---- mma over the 2 k16-steps of this stage ----
        #pragma unroll
        for (int kk = 0; kk < 2; kk++) {
            uint32_t ah[2][4], al[2][4], bh[4][2], bl[4][2];
            #pragma unroll
            for (int mt4 = 0; mt4 < 2; mt4++) {
                int mt = wm*2 + mt4;
                #pragma unroll
                for (int ai = 0; ai < 4; ai++) {
                    uint2 v = cA[(((kk*4 + mt)*4 + ai) << 5) + lane];
                    ah[mt4][ai] = v.x;
                    al[mt4][ai] = v.y;
                }
            }
            #pragma unroll
            for (int nt4 = 0; nt4 < 4; nt4++) {
                int nt = wn*4 + nt4;
                #pragma unroll
                for (int bi = 0; bi < 2; bi++) {
                    uint2 v = cB[(((kk*16 + nt)*2 + bi) << 5) + lane];
                    bh[nt4][bi] = v.x;
                    bl[nt4][bi] = v.y;
                }
            }
            #pragma unroll
            for (int mt4 = 0; mt4 < 2; mt4++)
                #pragma unroll
                for (int nt4 = 0; nt4 < 4; nt4++)
                    mma16(acc[mt4][nt4], ah[mt4], bh[nt4]);
            #pragma unroll
            for (int mt4 = 0; mt4 < 2; mt4++)
                #pragma unroll
                for (int nt4 = 0; nt4 < 4; nt4++)
                    mma16(acc[mt4][nt4], ah[mt4], bl[nt4]);
            #pragma unroll
            for (int mt4 = 0; mt4 < 2; mt4++)
                #pragma unroll
                for (int nt4 = 0; nt4 < 4; nt4++)
                    mma16(acc[mt4][nt4], al[mt4], bh[nt4]);
        }

        // ---- fill the other stage (read by mma at it+1) ----
        if (more) {
            uint2* nA = (uint2*)(dsmem + (p^1)*GEMM_STAGE_BYTES);
            uint2* nB = (uint2*)(dsmem + (p^1)*GEMM_STAGE_BYTES + 8192);
            #pragma unroll
            for (int t = 0; t < 2; t++) *(uint4*)(nA + offA[t]) = split4(gA[t]);
            #pragma unroll
            for (int t = 0; t < 4; t++) *(uint4*)(nB + offB[t]) = split4(gB[t]);
        }
        __syncthreads();
    }

    // ---- epilogue ----
    #pragma unroll
    for (int mt4 = 0; mt4 < 2; mt4++) {
        const int mlo = m0 + wm*32 + mt4*16 + gr;
        const int mhi = mlo + 8;
        #pragma unroll
        for (int nt4 = 0; nt4 < 4; nt4++) {
            const int nn = n0 + wn*32 + nt4*8 + tg*2;
            const float* d = acc[mt4][nt4];
            if (EPI == 0) {
                const int which = n0 >> 10;
                float* dst = (which == 0) ? g_q : ((which == 1) ? g_k : g_v);
                const int nl = nn & 1023;
                const int h  = nl >> 6;
                const int dd = nl & (HDIM - 1);
                {
                    int b = mlo >> 11, s = mlo & (SEQ - 1);
                    *(float2*)&dst[(((b*NHEAD + h)*SEQ) + s)*HDIM + dd] =
                        make_float2(d[0], d[1]);
                }
                {
                    int b = mhi >> 11, s = mhi & (SEQ - 1);
                    *(float2*)&dst[(((b*NHEAD + h)*SEQ) + s)*HDIM + dd] =
                        make_float2(d[2], d[3]);
                }
            } else {
                float2 bv = *(const float2*)&bias[nn];
                *(float2*)&out[(size_t)mlo * Nfull + nn] =
                    make_float2(d[0] + bv.x, d[1] + bv.y);
                *(float2*)&out[(size_t)mhi * Nfull + nn] =
                    make_float2(d[2] + bv.x, d[3] + bv.y);
            }
        }
    }
}

// ===========================================================================
// Causal flash attention on tensor cores (3xFP16, m16n8k16) — R9 winner,
// now with __launch_bounds__(256,2) to allow 2 co-resident CTAs (regs
// capped at 128; smem 2x64KB = 128KB <= 228KB).
// ===========================================================================
#define FLASH_SMEM_BYTES 65536

__global__ __launch_bounds__(256, 2) void flash_mma_kernel()
{
    extern __shared__ char fsm[];
    uint2* sQ = (uint2*)(fsm);             // 4096 uint2
    uint2* sK = (uint2*)(fsm + 32768);     // 2048 uint2
    uint2* sV = (uint2*)(fsm + 49152);     // 2048 uint2

    const int qt = blockIdx.x;
    const int h  = blockIdx.y;
    const int b  = blockIdx.z;
    const int bh = b*NHEAD + h;
    const float* Qg = g_q + (size_t)bh * SEQ * HDIM;
    const float* Kg = g_k + (size_t)bh * SEQ * HDIM;
    const float* Vg = g_v + (size_t)bh * SEQ * HDIM;

    const int tid  = threadIdx.x;
    const int w    = tid >> 5;
    const int lane = tid & 31;
    const int gr   = lane >> 2;
    const int tg   = lane & 3;
    const int q0   = qt * 128;

    // ---- fill Q fragments once (x8 scale folded) ----
    #pragma unroll
    for (int t = 0; t < 8; t++) {
        int idx = tid + t * 256;       // 0..2047 float4 slots
        int row = idx >> 4;            // 0..127
        int c4  = idx & 15;
        float4 v = *(const float4*)(Qg + (size_t)(q0 + row)*HDIM + c4*4);
        v.x *= 8.f; v.y *= 8.f; v.z *= 8.f; v.w *= 8.f;
        int kk  = c4 >> 2;
        int kw4 = c4 & 3;
        int aih = kw4 >> 1;
        int tg0 = (kw4 & 1) * 2;
        int mt = row >> 4, rw = row & 15;
        int ai = (rw >> 3) | (aih << 1);
        *(uint4*)(sQ + (((kk*8 + mt)*4 + ai) << 5) + (rw & 7)*4 + tg0) = split4(v);
    }

    float m0 = -1e30f, m1 = -1e30f, l0 = 0.f, l1 = 0.f;
    float cacc[8][4];
    #pragma unroll
    for (int nt = 0; nt < 8; nt++)
        #pragma unroll
        for (int v = 0; v < 4; v++) cacc[nt][v] = 0.f;

    const int qrow0 = q0 + 16*w + gr;
    const int nkt   = 2*qt + 2;

    for (int kt = 0; kt < nkt; kt++) {
        const int k0 = kt * 64;
        __syncthreads();

        // ---- fill K fragments: B-operand (k=d, n=key) ----
        #pragma unroll
        for (int t = 0; t < 4; t++) {
            int idx = tid + t * 256;
            int row = idx >> 4;
            int c4  = idx & 15;
            float4 v = *(const float4*)(Kg + (size_t)(k0 + row)*HDIM + c4*4);
            int kk  = c4 >> 2;
            int kw4 = c4 & 3;
            int bi  = kw4 >> 1;
            int tg0 = (kw4 & 1) * 2;
            int nt  = row >> 3;
            *(uint4*)(sK + (((kk*8 + nt)*2 + bi) << 5) + (row & 7)*4 + tg0) = split4(v);
        }

        // ---- fill V fragments: B-operand (k=key, n=d); key-pair transpose ----
        #pragma unroll
        for (int t = 0; t < 2; t++) {
            int idx = tid + t * 256;
            int kp  = idx >> 4;
            int c4  = idx & 15;
            float4 v0 = *(const float4*)(Vg + (size_t)(k0 + 2*kp  )*HDIM + c4*4);
            float4 v1 = *(const float4*)(Vg + (size_t)(k0 + 2*kp+1)*HDIM + c4*4);
            int kkv = kp >> 3;
            int tgp = kp & 7;
            int bi  = tgp >> 2;
            int tgv = tgp & 3;
            const float a0[4] = {v0.x, v0.y, v0.z, v0.w};
            const float a1[4] = {v1.x, v1.y, v1.z, v1.w};
            #pragma unroll
            for (int j = 0; j < 4; j++) {
                int d  = c4*4 + j;
                int nt = d >> 3;
                int grv = d & 7;
                uint32_t hh, ll;
                pack_hl(a0[j], a1[j], hh, ll);
                int ln = (grv*4 + tgv) ^ ((nt & 3) << 2);
                sV[(((kkv*8 + nt)*2 + bi) << 5) + ln] = make_uint2(hh, ll);
            }
        }
        __syncthreads();

        if (k0 <= q0 + 16*w + 15) {
            // ---- S = (16q) @ K^T via 3xFP16 ----
            float sacc[8][4];
            #pragma unroll
            for (int nt = 0; nt < 8; nt++)
                #pragma unroll
                for (int v = 0; v < 4; v++) sacc[nt][v] = 0.f;

            #pragma unroll
            for (int kk = 0; kk < 4; kk++) {
                uint32_t qh[4], ql[4], kh[8][2], kl[8][2];
                #pragma unroll
                for (int ai = 0; ai < 4; ai++) {
                    uint2 v = sQ[(((kk*8 + w)*4 + ai) << 5) + lane];
                    qh[ai] = v.x; ql[ai] = v.y;
                }
                #pragma unroll
                for (int nt = 0; nt < 8; nt++)
                    #pragma unroll
                    for (int bi = 0; bi < 2; bi++) {
                        uint2 v = sK[(((kk*8 + nt)*2 + bi) << 5) + lane];
                        kh[nt][bi] = v.x; kl[nt][bi] = v.y;
                    }
                #pragma unroll
                for (int nt = 0; nt < 8; nt++) mma16(sacc[nt], qh, kh[nt]);
                #pragma unroll
                for (int nt = 0; nt < 8; nt++) mma16(sacc[nt], qh, kl[nt]);
                #pragma unroll
                for (int nt = 0; nt < 8; nt++) mma16(sacc[nt], ql, kh[nt]);
            }

            // ---- causal mask (diagonal region only) ----
            if (k0 + 63 > qrow0 || k0 + 63 > qrow0 + 8) {
                #pragma unroll
                for (int nt = 0; nt < 8; nt++) {
                    int c = k0 + nt*8 + 2*tg;
                    if (c     > qrow0    ) sacc[nt][0] = -1e30f;
                    if (c + 1 > qrow0    ) sacc[nt][1] = -1e30f;
                    if (c     > qrow0 + 8) sacc[nt][2] = -1e30f;
                    if (c + 1 > qrow0 + 8) sacc[nt][3] = -1e30f;
                }
            }

            // ---- online softmax (rows gr, gr+8; reduce over 4 tg lanes) ----
            float mx0 = -1e30f, mx1 = -1e30f;
            #pragma unroll
            for (int nt = 0; nt < 8; nt++) {
                mx0 = fmaxf(mx0, fmaxf(sacc[nt][0], sacc[nt][1]));
                mx1 = fmaxf(mx1, fmaxf(sacc[nt][2], sacc[nt][3]));
            }
            mx0 = fmaxf(mx0, __shfl_xor_sync(0xffffffffu, mx0, 1));
            mx0 = fmaxf(mx0, __shfl_xor_sync(0xffffffffu, mx0, 2));
            mx1 = fmaxf(mx1, __shfl_xor_sync(0xffffffffu, mx1, 1));
            mx1 = fmaxf(mx1, __shfl_xor_sync(0xffffffffu, mx1, 2));
            float mn0 = fmaxf(m0, mx0), mn1 = fmaxf(m1, mx1);
            float al0 = __expf(m0 - mn0), al1 = __expf(m1 - mn1);
            m0 = mn0; m1 = mn1;

            float rs0 = 0.f, rs1 = 0.f;
            #pragma unroll
            for (int nt = 0; nt < 8; nt++) {
                sacc[nt][0] = __expf(sacc[nt][0] - mn0); rs0 += sacc[nt][0];
                sacc[nt][1] = __expf(sacc[nt][1] - mn0); rs0 += sacc[nt][1];
                sacc[nt][2] = __expf(sacc[nt][2] - mn1); rs1 += sacc[nt][2];
                sacc[nt][3] = __expf(sacc[nt][3] - mn1); rs1 += sacc[nt][3];
            }
            rs0 += __shfl_xor_sync(0xffffffffu, rs0, 1);
            rs0 += __shfl_xor_sync(0xffffffffu, rs0, 2);
            rs1 += __shfl_xor_sync(0xffffffffu, rs1, 1);
            rs1 += __shfl_xor_sync(0xffffffffu, rs1, 2);
            l0 = l0 * al0 + rs0;
            l1 = l1 * al1 + rs1;

            #pragma unroll
            for (int nt = 0; nt < 8; nt++) {
                cacc[nt][0] *= al0; cacc[nt][1] *= al0;
                cacc[nt][2] *= al1; cacc[nt][3] *= al1;
            }

            // ---- PV: P frags straight from registers; 3xFP16 ----
            #pragma unroll
            for (int kkv = 0; kkv < 4; kkv++) {
                uint32_t ph[4], pl[4], vh[8][2], vl[8][2];
                pack_hl(sacc[2*kkv  ][0], sacc[2*kkv  ][1], ph[0], pl[0]);
                pack_hl(sacc[2*kkv  ][2], sacc[2*kkv  ][3], ph[1], pl[1]);
                pack_hl(sacc[2*kkv+1][0], sacc[2*kkv+1][1], ph[2], pl[2]);
                pack_hl(sacc[2*kkv+1][2], sacc[2*kkv+1][3], ph[3], pl[3]);
                #pragma unroll
                for (int nt = 0; nt < 8; nt++) {
                    int ln = lane ^ ((nt & 3) << 2);
                    #pragma unroll
                    for (int bi = 0; bi < 2; bi++) {
                        uint2 v = sV[(((kkv*8 + nt)*2 + bi) << 5) + ln];
                        vh[nt][bi] = v.x; vl[nt][bi] = v.y;
                    }
                }
                #pragma unroll
                for (int nt = 0; nt < 8; nt++) mma16(cacc[nt], ph, vh[nt]);
                #pragma unroll
                for (int nt = 0; nt < 8; nt++) mma16(cacc[nt], ph, vl[nt]);
                #pragma unroll
                for (int nt = 0; nt < 8; nt++) mma16(cacc[nt], pl, vh[nt]);
            }
        }
    }

    // ---- epilogue: ctx[b][s][h*64+d] = acc / l ----
    const float inv0 = 1.0f / l0;
    const float inv1 = 1.0f / l1;
    float* o0 = g_ctx + ((size_t)(b*SEQ + qrow0    )) * EMB + h*HDIM;
    float* o1 = g_ctx + ((size_t)(b*SEQ + qrow0 + 8)) * EMB + h*HDIM;
    #pragma unroll
    for (int nt = 0; nt < 8; nt++) {
        int d = nt*8 + 2*tg;
        *(float2*)(o0 + d) = make_float2(cacc[nt][0]*inv0, cacc[nt][1]*inv0);
        *(float2*)(o1 + d) = make_float2(cacc[nt][2]*inv1, cacc[nt][3]*inv1);
    }
}

// ---------------------------------------------------------------------------
// Inputs (metadata order): x [2,2048,1024] f32, w_qkv [3072,1024] f32,
// w_proj [1024,1024] f32, b_proj [1024] f32. Output: [2,2048,1024] f32.
// ---------------------------------------------------------------------------
extern "C" void kernel_launch(void* const* d_in, const int* in_sizes, int n_in,
                              void* d_out, int out_size)
{
    (void)in_sizes; (void)n_in; (void)out_size;
    const float* x      = (const float*)d_in[0];
    const float* w_qkv  = (const float*)d_in[1];
    const float* w_proj = (const float*)d_in[2];
    const float* b_proj = (const float*)d_in[3];
    float* out = (float*)d_out;

    cudaFuncSetAttribute(mma_gemm_kernel<0>,
                         cudaFuncAttributeMaxDynamicSharedMemorySize, GEMM_SMEM_BYTES);
    cudaFuncSetAttribute(mma_gemm_kernel<1>,
                         cudaFuncAttributeMaxDynamicSharedMemorySize, GEMM_SMEM_BYTES);
    cudaFuncSetAttribute(flash_mma_kernel,
                         cudaFuncAttributeMaxDynamicSharedMemorySize, FLASH_SMEM_BYTES);

    // 1) QKV GEMM (3xFP16 mma.sync): [4096,1024] @ [3072,1024]^T -> g_q/g_k/g_v
    dim3 g1((3*EMB)/128, MTOT/64);
    mma_gemm_kernel<0><<<g1, 256, GEMM_SMEM_BYTES>>>(x, w_qkv, nullptr, nullptr,
                                                     EMB, 3*EMB);

    // 2) Causal flash attention (3xFP16 mma.sync) -> g_ctx
    dim3 g2(SEQ/128, NHEAD, BATCH);
    flash_mma_kernel<<<g2, 256, FLASH_SMEM_BYTES>>>();

    // 3) Proj GEMM + bias (3xFP16 mma.sync): g_ctx @ w_proj^T + b_proj -> out
    dim3 g3(EMB/128, MTOT/64);
    mma_gemm_kernel<1><<<g3, 256, GEMM_SMEM_BYTES>>>(nullptr, w_proj, b_proj, out,
                                                     EMB, EMB);
}

// round 12
// speedup vs baseline: 1.1107x; 1.1107x over previous
#include <cuda_runtime.h>
#include <cuda_fp16.h>
#include <math.h>
#include <stdint.h>

#define BATCH 2
#define SEQ   2048
#define EMB   1024
#define NHEAD 16
#define HDIM  64
#define MTOT  (BATCH*SEQ)   // 4096

// Scratch (allocation-free contract: __device__ globals)
__device__ float g_q[BATCH*NHEAD*SEQ*HDIM];   // [b][h][s][d]
__device__ float g_k[BATCH*NHEAD*SEQ*HDIM];
__device__ float g_v[BATCH*NHEAD*SEQ*HDIM];
__device__ float g_ctx[(size_t)MTOT*EMB];     // [b*s][e]

// ===========================================================================
// m16n8k16 fp16 mma.sync, fp32 accumulate. Calibrated R5-R10: the sm_103
// legacy-HMMA path runs at a FIXED ~0.18 mma/cyc/SM regardless of occupancy
// or buffering — wall time is proportional to mma instruction count.
// ===========================================================================
__device__ __forceinline__ void mma16(float* d, const uint32_t* a, const uint32_t* b) {
    asm volatile(
        "mma.sync.aligned.m16n8k16.row.col.f32.f16.f16.f32 "
        "{%0,%1,%2,%3}, {%4,%5,%6,%7}, {%8,%9}, {%0,%1,%2,%3};"
        : "+f"(d[0]), "+f"(d[1]), "+f"(d[2]), "+f"(d[3])
        : "r"(a[0]), "r"(a[1]), "r"(a[2]), "r"(a[3]), "r"(b[0]), "r"(b[1]));
}

// Split float4 into fp16 (hi, lo) pair-packed b32 words.
__device__ __forceinline__ uint4 split4(float4 g) {
    __half2 h01 = __floats2half2_rn(g.x, g.y);
    __half2 h23 = __floats2half2_rn(g.z, g.w);
    float2 f01 = __half22float2(h01);
    float2 f23 = __half22float2(h23);
    __half2 l01 = __floats2half2_rn(g.x - f01.x, g.y - f01.y);
    __half2 l23 = __floats2half2_rn(g.z - f23.x, g.w - f23.y);
    uint4 r;
    r.x = *reinterpret_cast<uint32_t*>(&h01);
    r.y = *reinterpret_cast<uint32_t*>(&l01);
    r.z = *reinterpret_cast<uint32_t*>(&h23);
    r.w = *reinterpret_cast<uint32_t*>(&l23);
    return r;
}

// Pack two fp32 into fp16 hi-pair + lo-pair b32 words (register-only).
__device__ __forceinline__ void pack_hl(float x, float y, uint32_t& h, uint32_t& l) {
    __half2 hh = __floats2half2_rn(x, y);
    float2 f = __half22float2(hh);
    __half2 ll = __floats2half2_rn(x - f.x, y - f.y);
    h = *reinterpret_cast<uint32_t*>(&hh);
    l = *reinterpret_cast<uint32_t*>(&ll);
}

// ===========================================================================
// 3xFP16 mma.sync GEMM, double-buffered — EXACT R9 configuration (the best
// measured: QKV 362us, proj 120us). 128x128 CTA, BK=32, 512 threads = 16
// warps (4x4), warp tile 32x32. R10's 64x128/2-CTA variant REGRESSED
// (B-traffic doubled, no latency benefit) and is reverted.
// ===========================================================================
#define GEMM_STAGE_BYTES 32768
#define GEMM_SMEM_BYTES  (2*GEMM_STAGE_BYTES)   // 64 KB

template<int EPI>
__global__ __launch_bounds__(512) void mma_gemm_kernel(
    const float* __restrict__ Ain,
    const float* __restrict__ W,
    const float* __restrict__ bias,
    float* __restrict__ out,
    int K, int Nfull)
{
    extern __shared__ char dsmem[];
    const float* A = (EPI == 1) ? (const float*)g_ctx : Ain;

    const int tid  = threadIdx.x;
    const int wid  = tid >> 5;
    const int lane = tid & 31;
    const int wm   = wid & 3;
    const int wn   = wid >> 2;
    const int gr   = lane >> 2;
    const int tg   = lane & 3;
    const int m0   = blockIdx.y * 128;
    const int n0   = blockIdx.x * 128;

    const float *pA[2], *pB[2];
    int offA[2], offB[2];
    #pragma unroll
    for (int t = 0; t < 2; t++) {
        int idx = tid + t * 512;
        int row = idx >> 3;
        int c4  = idx & 7;
        pA[t] = A + (size_t)(m0 + row) * K + c4 * 4;
        pB[t] = W + (size_t)(n0 + row) * K + c4 * 4;
        int kk  = c4 >> 2;
        int kw4 = c4 & 3;
        int aih = kw4 >> 1;
        int tg0 = (kw4 & 1) * 2;
        int mt = row >> 4, rw = row & 15;
        int ai = (rw >> 3) | (aih << 1);
        offA[t] = (((kk*8 + mt)*4 + ai) << 5) + (rw & 7)*4 + tg0;
        int nt = row >> 3;
        offB[t] = (((kk*16 + nt)*2 + aih) << 5) + (row & 7)*4 + tg0;
    }

    float acc[2][4][4];
    #pragma unroll
    for (int i = 0; i < 2; i++)
        #pragma unroll
        for (int j = 0; j < 4; j++)
            #pragma unroll
            for (int v = 0; v < 4; v++) acc[i][j][v] = 0.f;

    float4 gA[2], gB[2];
    #pragma unroll
    for (int t = 0; t < 2; t++) {
        gA[t] = *(const float4*)(pA[t]);
        gB[t] = *(const float4*)(pB[t]);
    }
    {
        uint2* sA0 = (uint2*)(dsmem);
        uint2* sB0 = (uint2*)(dsmem + 16384);
        #pragma unroll
        for (int t = 0; t < 2; t++) {
            *(uint4*)(sA0 + offA[t]) = split4(gA[t]);
            *(uint4*)(sB0 + offB[t]) = split4(gB[t]);
        }
    }
    __syncthreads();

    const int niter = K >> 5;
    for (int it = 0; it < niter; it++) {
        const int p = it & 1;
        uint2* cA = (uint2*)(dsmem + p*GEMM_STAGE_BYTES);
        uint2* cB = (uint2*)(dsmem + p*GEMM_STAGE_BYTES + 16384);
        const bool more = (it + 1 < niter);

        if (more) {
            const int ko = (it + 1) << 5;
            #pragma unroll
            for (int t = 0; t < 2; t++) {
                gA[t] = *(const float4*)(pA[t] + ko);
                gB[t] = *(const float4*)(pB[t] + ko);
            }
        }

        #pragma unroll
        for (int kk = 0; kk < 2; kk++) {
            uint32_t ah[2][4], al[2][4], bh[4][2], bl[4][2];
            #pragma unroll
            for (int mt4 = 0; mt4 < 2; mt4++) {
                int mt = wm*2 + mt4;
                #pragma unroll
                for (int ai = 0; ai < 4; ai++) {
                    uint2 v = cA[(((kk*8 + mt)*4 + ai) << 5) + lane];
                    ah[mt4][ai] = v.x;
                    al[mt4][ai] = v.y;
                }
            }
            #pragma unroll
            for (int nt4 = 0; nt4 < 4; nt4++) {
                int nt = wn*4 + nt4;
                #pragma unroll
                for (int bi = 0; bi < 2; bi++) {
                    uint2 v = cB[(((kk*16 + nt)*2 + bi) << 5) + lane];
                    bh[nt4][bi] = v.x;
                    bl[nt4][bi] = v.y;
                }
            }
            #pragma unroll
            for (int mt4 = 0; mt4 < 2; mt4++)
                #pragma unroll
                for (int nt4 = 0; nt4 < 4; nt4++)
                    mma16(acc[mt4][nt4], ah[mt4], bh[nt4]);
            #pragma unroll
            for (int mt4 = 0; mt4 < 2; mt4++)
                #pragma unroll
                for (int nt4 = 0; nt4 < 4; nt4++)
                    mma16(acc[mt4][nt4], ah[mt4], bl[nt4]);
            #pragma unroll
            for (int mt4 = 0; mt4 < 2; mt4++)
                #pragma unroll
                for (int nt4 = 0; nt4 < 4; nt4++)
                    mma16(acc[mt4][nt4], al[mt4], bh[nt4]);
        }

        if (more) {
            uint2* nA = (uint2*)(dsmem + (p^1)*GEMM_STAGE_BYTES);
            uint2* nB = (uint2*)(dsmem + (p^1)*GEMM_STAGE_BYTES + 16384);
            #pragma unroll
            for (int t = 0; t < 2; t++) {
                *(uint4*)(nA + offA[t]) = split4(gA[t]);
                *(uint4*)(nB + offB[t]) = split4(gB[t]);
            }
        }
        __syncthreads();
    }

    #pragma unroll
    for (int mt4 = 0; mt4 < 2; mt4++) {
        const int mlo = m0 + wm*32 + mt4*16 + gr;
        const int mhi = mlo + 8;
        #pragma unroll
        for (int nt4 = 0; nt4 < 4; nt4++) {
            const int nn = n0 + wn*32 + nt4*8 + tg*2;
            const float* d = acc[mt4][nt4];
            if (EPI == 0) {
                const int which = n0 >> 10;
                float* dst = (which == 0) ? g_q : ((which == 1) ? g_k : g_v);
                const int nl = nn & 1023;
                const int h  = nl >> 6;
                const int dd = nl & (HDIM - 1);
                {
                    int b = mlo >> 11, s = mlo & (SEQ - 1);
                    *(float2*)&dst[(((b*NHEAD + h)*SEQ) + s)*HDIM + dd] =
                        make_float2(d[0], d[1]);
                }
                {
                    int b = mhi >> 11, s = mhi & (SEQ - 1);
                    *(float2*)&dst[(((b*NHEAD + h)*SEQ) + s)*HDIM + dd] =
                        make_float2(d[2], d[3]);
                }
            } else {
                float2 bv = *(const float2*)&bias[nn];
                *(float2*)&out[(size_t)mlo * Nfull + nn] =
                    make_float2(d[0] + bv.x, d[1] + bv.y);
                *(float2*)&out[(size_t)mhi * Nfull + nn] =
                    make_float2(d[2] + bv.x, d[3] + bv.y);
            }
        }
    }
}

// ===========================================================================
// Causal flash attention on tensor cores — R9 base, with the PV V-lo pass
// DROPPED (R11 change): PV = ph*vh + pl*vh (2 passes). Per-term error from
// the dropped p*v_lo term is <=2^-11|pv| random-sign -> ctx rel err ~2.8e-4
// (S path stays 3-pass: softmax amplifies score errors x8). V is stored
// hi-only in smem (uint32): tile halves to 8KB and the fill loses its lo
// pack work. Saves 2.1M mma ~= 47us at the calibrated instruction rate.
// ===========================================================================
#define FLASH_SMEM_BYTES 57344   // Q 32K + K 16K + V 8K

__global__ __launch_bounds__(256) void flash_mma_kernel()
{
    extern __shared__ char fsm[];
    uint2*    sQ = (uint2*)(fsm);              // 4096 uint2
    uint2*    sK = (uint2*)(fsm + 32768);      // 2048 uint2
    uint32_t* sV = (uint32_t*)(fsm + 49152);   // 2048 uint32 (hi only)

    const int qt = blockIdx.x;
    const int h  = blockIdx.y;
    const int b  = blockIdx.z;
    const int bh = b*NHEAD + h;
    const float* Qg = g_q + (size_t)bh * SEQ * HDIM;
    const float* Kg = g_k + (size_t)bh * SEQ * HDIM;
    const float* Vg = g_v + (size_t)bh * SEQ * HDIM;

    const int tid  = threadIdx.x;
    const int w    = tid >> 5;
    const int lane = tid & 31;
    const int gr   = lane >> 2;
    const int tg   = lane & 3;
    const int q0   = qt * 128;

    // ---- fill Q fragments once (x8 scale folded) ----
    #pragma unroll
    for (int t = 0; t < 8; t++) {
        int idx = tid + t * 256;       // 0..2047 float4 slots
        int row = idx >> 4;            // 0..127
        int c4  = idx & 15;
        float4 v = *(const float4*)(Qg + (size_t)(q0 + row)*HDIM + c4*4);
        v.x *= 8.f; v.y *= 8.f; v.z *= 8.f; v.w *= 8.f;
        int kk  = c4 >> 2;
        int kw4 = c4 & 3;
        int aih = kw4 >> 1;
        int tg0 = (kw4 & 1) * 2;
        int mt = row >> 4, rw = row & 15;
        int ai = (rw >> 3) | (aih << 1);
        *(uint4*)(sQ + (((kk*8 + mt)*4 + ai) << 5) + (rw & 7)*4 + tg0) = split4(v);
    }

    float m0 = -1e30f, m1 = -1e30f, l0 = 0.f, l1 = 0.f;
    float cacc[8][4];
    #pragma unroll
    for (int nt = 0; nt < 8; nt++)
        #pragma unroll
        for (int v = 0; v < 4; v++) cacc[nt][v] = 0.f;

    const int qrow0 = q0 + 16*w + gr;   // thread's low row
    const int nkt   = 2*qt + 2;         // causal kv-tile count

    for (int kt = 0; kt < nkt; kt++) {
        const int k0 = kt * 64;
        __syncthreads();   // previous iteration's mma reads complete

        // ---- fill K fragments: B-operand (k=d, n=key), (hi,lo) ----
        #pragma unroll
        for (int t = 0; t < 4; t++) {
            int idx = tid + t * 256;   // 0..1023
            int row = idx >> 4;        // key 0..63
            int c4  = idx & 15;
            float4 v = *(const float4*)(Kg + (size_t)(k0 + row)*HDIM + c4*4);
            int kk  = c4 >> 2;
            int kw4 = c4 & 3;
            int bi  = kw4 >> 1;
            int tg0 = (kw4 & 1) * 2;
            int nt  = row >> 3;
            *(uint4*)(sK + (((kk*8 + nt)*2 + bi) << 5) + (row & 7)*4 + tg0) = split4(v);
        }

        // ---- fill V fragments: B-operand (k=key, n=d), HI ONLY; key-pair
        //      transposed; bank-swizzled ----
        #pragma unroll
        for (int t = 0; t < 2; t++) {
            int idx = tid + t * 256;   // 0..511
            int kp  = idx >> 4;        // key pair 0..31
            int c4  = idx & 15;        // d/4
            float4 v0 = *(const float4*)(Vg + (size_t)(k0 + 2*kp  )*HDIM + c4*4);
            float4 v1 = *(const float4*)(Vg + (size_t)(k0 + 2*kp+1)*HDIM + c4*4);
            int kkv = kp >> 3;
            int tgp = kp & 7;
            int bi  = tgp >> 2;
            int tgv = tgp & 3;
            const float a0[4] = {v0.x, v0.y, v0.z, v0.w};
            const float a1[4] = {v1.x, v1.y, v1.z, v1.w};
            #pragma unroll
            for (int j = 0; j < 4; j++) {
                int d  = c4*4 + j;
                int nt = d >> 3;
                int grv = d & 7;
                __half2 hh = __floats2half2_rn(a0[j], a1[j]);
                int ln = (grv*4 + tgv) ^ ((nt & 3) << 2);   // bank swizzle
                sV[(((kkv*8 + nt)*2 + bi) << 5) + ln] =
                    *reinterpret_cast<uint32_t*>(&hh);
            }
        }
        __syncthreads();

        // warps whose rows are entirely left of this kv tile: skip compute
        if (k0 <= q0 + 16*w + 15) {
            // ---- S = (16q) @ K^T via 3xFP16 ----
            float sacc[8][4];
            #pragma unroll
            for (int nt = 0; nt < 8; nt++)
                #pragma unroll
                for (int v = 0; v < 4; v++) sacc[nt][v] = 0.f;

            #pragma unroll
            for (int kk = 0; kk < 4; kk++) {
                uint32_t qh[4], ql[4], kh[8][2], kl[8][2];
                #pragma unroll
                for (int ai = 0; ai < 4; ai++) {
                    uint2 v = sQ[(((kk*8 + w)*4 + ai) << 5) + lane];
                    qh[ai] = v.x; ql[ai] = v.y;
                }
                #pragma unroll
                for (int nt = 0; nt < 8; nt++)
                    #pragma unroll
                    for (int bi = 0; bi < 2; bi++) {
                        uint2 v = sK[(((kk*8 + nt)*2 + bi) << 5) + lane];
                        kh[nt][bi] = v.x; kl[nt][bi] = v.y;
                    }
                #pragma unroll
                for (int nt = 0; nt < 8; nt++) mma16(sacc[nt], qh, kh[nt]);
                #pragma unroll
                for (int nt = 0; nt < 8; nt++) mma16(sacc[nt], qh, kl[nt]);
                #pragma unroll
                for (int nt = 0; nt < 8; nt++) mma16(sacc[nt], ql, kh[nt]);
            }

            // ---- causal mask (diagonal region only) ----
            if (k0 + 63 > qrow0 || k0 + 63 > qrow0 + 8) {
                #pragma unroll
                for (int nt = 0; nt < 8; nt++) {
                    int c = k0 + nt*8 + 2*tg;
                    if (c     > qrow0    ) sacc[nt][0] = -1e30f;
                    if (c + 1 > qrow0    ) sacc[nt][1] = -1e30f;
                    if (c     > qrow0 + 8) sacc[nt][2] = -1e30f;
                    if (c + 1 > qrow0 + 8) sacc[nt][3] = -1e30f;
                }
            }

            // ---- online softmax (rows gr, gr+8; reduce over 4 tg lanes) ----
            float mx0 = -1e30f, mx1 = -1e30f;
            #pragma unroll
            for (int nt = 0; nt < 8; nt++) {
                mx0 = fmaxf(mx0, fmaxf(sacc[nt][0], sacc[nt][1]));
                mx1 = fmaxf(mx1, fmaxf(sacc[nt][2], sacc[nt][3]));
            }
            mx0 = fmaxf(mx0, __shfl_xor_sync(0xffffffffu, mx0, 1));
            mx0 = fmaxf(mx0, __shfl_xor_sync(0xffffffffu, mx0, 2));
            mx1 = fmaxf(mx1, __shfl_xor_sync(0xffffffffu, mx1, 1));
            mx1 = fmaxf(mx1, __shfl_xor_sync(0xffffffffu, mx1, 2));
            float mn0 = fmaxf(m0, mx0), mn1 = fmaxf(m1, mx1);
            float al0 = __expf(m0 - mn0), al1 = __expf(m1 - mn1);
            m0 = mn0; m1 = mn1;

            float rs0 = 0.f, rs1 = 0.f;
            #pragma unroll
            for (int nt = 0; nt < 8; nt++) {
                sacc[nt][0] = __expf(sacc[nt][0] - mn0); rs0 += sacc[nt][0];
                sacc[nt][1] = __expf(sacc[nt][1] - mn0); rs0 += sacc[nt][1];
                sacc[nt][2] = __expf(sacc[nt][2] - mn1); rs1 += sacc[nt][2];
                sacc[nt][3] = __expf(sacc[nt][3] - mn1); rs1 += sacc[nt][3];
            }
            rs0 += __shfl_xor_sync(0xffffffffu, rs0, 1);
            rs0 += __shfl_xor_sync(0xffffffffu, rs0, 2);
            rs1 += __shfl_xor_sync(0xffffffffu, rs1, 1);
            rs1 += __shfl_xor_sync(0xffffffffu, rs1, 2);
            l0 = l0 * al0 + rs0;
            l1 = l1 * al1 + rs1;

            #pragma unroll
            for (int nt = 0; nt < 8; nt++) {
                cacc[nt][0] *= al0; cacc[nt][1] *= al0;
                cacc[nt][2] *= al1; cacc[nt][3] *= al1;
            }

            // ---- PV (2-pass): P (hi,lo) from registers x V hi ----
            #pragma unroll
            for (int kkv = 0; kkv < 4; kkv++) {
                uint32_t ph[4], pl[4], vh[8][2];
                pack_hl(sacc[2*kkv  ][0], sacc[2*kkv  ][1], ph[0], pl[0]);
                pack_hl(sacc[2*kkv  ][2], sacc[2*kkv  ][3], ph[1], pl[1]);
                pack_hl(sacc[2*kkv+1][0], sacc[2*kkv+1][1], ph[2], pl[2]);
                pack_hl(sacc[2*kkv+1][2], sacc[2*kkv+1][3], ph[3], pl[3]);
                #pragma unroll
                for (int nt = 0; nt < 8; nt++) {
                    int ln = lane ^ ((nt & 3) << 2);
                    #pragma unroll
                    for (int bi = 0; bi < 2; bi++)
                        vh[nt][bi] = sV[(((kkv*8 + nt)*2 + bi) << 5) + ln];
                }
                #pragma unroll
                for (int nt = 0; nt < 8; nt++) mma16(cacc[nt], ph, vh[nt]);
                #pragma unroll
                for (int nt = 0; nt < 8; nt++) mma16(cacc[nt], pl, vh[nt]);
            }
        }
    }

    // ---- epilogue: ctx[b][s][h*64+d] = acc / l ----
    const float inv0 = 1.0f / l0;
    const float inv1 = 1.0f / l1;
    float* o0 = g_ctx + ((size_t)(b*SEQ + qrow0    )) * EMB + h*HDIM;
    float* o1 = g_ctx + ((size_t)(b*SEQ + qrow0 + 8)) * EMB + h*HDIM;
    #pragma unroll
    for (int nt = 0; nt < 8; nt++) {
        int d = nt*8 + 2*tg;
        *(float2*)(o0 + d) = make_float2(cacc[nt][0]*inv0, cacc[nt][1]*inv0);
        *(float2*)(o1 + d) = make_float2(cacc[nt][2]*inv1, cacc[nt][3]*inv1);
    }
}

// ---------------------------------------------------------------------------
// Inputs (metadata order): x [2,2048,1024] f32, w_qkv [3072,1024] f32,
// w_proj [1024,1024] f32, b_proj [1024] f32. Output: [2,2048,1024] f32.
// ---------------------------------------------------------------------------
extern "C" void kernel_launch(void* const* d_in, const int* in_sizes, int n_in,
                              void* d_out, int out_size)
{
    (void)in_sizes; (void)n_in; (void)out_size;
    const float* x      = (const float*)d_in[0];
    const float* w_qkv  = (const float*)d_in[1];
    const float* w_proj = (const float*)d_in[2];
    const float* b_proj = (const float*)d_in[3];
    float* out = (float*)d_out;

    cudaFuncSetAttribute(mma_gemm_kernel<0>,
                         cudaFuncAttributeMaxDynamicSharedMemorySize, GEMM_SMEM_BYTES);
    cudaFuncSetAttribute(mma_gemm_kernel<1>,
                         cudaFuncAttributeMaxDynamicSharedMemorySize, GEMM_SMEM_BYTES);
    cudaFuncSetAttribute(flash_mma_kernel,
                         cudaFuncAttributeMaxDynamicSharedMemorySize, FLASH_SMEM_BYTES);

    // 1) QKV GEMM (3xFP16 mma.sync): [4096,1024] @ [3072,1024]^T -> g_q/g_k/g_v
    dim3 g1((3*EMB)/128, MTOT/128);
    mma_gemm_kernel<0><<<g1, 512, GEMM_SMEM_BYTES>>>(x, w_qkv, nullptr, nullptr,
                                                     EMB, 3*EMB);

    // 2) Causal flash attention (3xFP16 S, 2-pass PV) -> g_ctx
    dim3 g2(SEQ/128, NHEAD, BATCH);
    flash_mma_kernel<<<g2, 256, FLASH_SMEM_BYTES>>>();

    // 3) Proj GEMM + bias (3xFP16 mma.sync): g_ctx @ w_proj^T + b_proj -> out
    dim3 g3(EMB/128, MTOT/128);
    mma_gemm_kernel<1><<<g3, 512, GEMM_SMEM_BYTES>>>(nullptr, w_proj, b_proj, out,
                                                     EMB, EMB);
}

// round 13
// speedup vs baseline: 1.1518x; 1.0370x over previous
#include <cuda_runtime.h>
#include <cuda_fp16.h>
#include <math.h>
#include <stdint.h>

#define BATCH 2
#define SEQ   2048
#define EMB   1024
#define NHEAD 16
#define HDIM  64
#define MTOT  (BATCH*SEQ)   // 4096

// Scratch (allocation-free contract: __device__ globals)
__device__ float g_q[BATCH*NHEAD*SEQ*HDIM];   // [b][h][s][d]
__device__ float g_k[BATCH*NHEAD*SEQ*HDIM];
__device__ float g_v[BATCH*NHEAD*SEQ*HDIM];
__device__ float g_ctx[(size_t)MTOT*EMB];     // [b*s][e]

// ===========================================================================
// m16n8k16 fp16 mma.sync, fp32 accumulate. Calibrated R5-R11: the sm_103
// legacy-HMMA path runs at a FIXED ~0.18 mma/cyc/SM regardless of occupancy
// or buffering — wall time is proportional to mma instruction count, so
// pass-count reduction (within the 1e-3 error budget) is THE lever.
// ===========================================================================
__device__ __forceinline__ void mma16(float* d, const uint32_t* a, const uint32_t* b) {
    asm volatile(
        "mma.sync.aligned.m16n8k16.row.col.f32.f16.f16.f32 "
        "{%0,%1,%2,%3}, {%4,%5,%6,%7}, {%8,%9}, {%0,%1,%2,%3};"
        : "+f"(d[0]), "+f"(d[1]), "+f"(d[2]), "+f"(d[3])
        : "r"(a[0]), "r"(a[1]), "r"(a[2]), "r"(a[3]), "r"(b[0]), "r"(b[1]));
}

// Split float4 into fp16 (hi, lo) pair-packed b32 words.
__device__ __forceinline__ uint4 split4(float4 g) {
    __half2 h01 = __floats2half2_rn(g.x, g.y);
    __half2 h23 = __floats2half2_rn(g.z, g.w);
    float2 f01 = __half22float2(h01);
    float2 f23 = __half22float2(h23);
    __half2 l01 = __floats2half2_rn(g.x - f01.x, g.y - f01.y);
    __half2 l23 = __floats2half2_rn(g.z - f23.x, g.w - f23.y);
    uint4 r;
    r.x = *reinterpret_cast<uint32_t*>(&h01);
    r.y = *reinterpret_cast<uint32_t*>(&l01);
    r.z = *reinterpret_cast<uint32_t*>(&h23);
    r.w = *reinterpret_cast<uint32_t*>(&l23);
    return r;
}

// Pack two fp32 into fp16 hi-pair + lo-pair b32 words (register-only).
__device__ __forceinline__ void pack_hl(float x, float y, uint32_t& h, uint32_t& l) {
    __half2 hh = __floats2half2_rn(x, y);
    float2 f = __half22float2(hh);
    __half2 ll = __floats2half2_rn(x - f.x, y - f.y);
    h = *reinterpret_cast<uint32_t*>(&hh);
    l = *reinterpret_cast<uint32_t*>(&ll);
}

// ===========================================================================
// FP16 mma.sync GEMM, double-buffered (R9 config: 128x128 CTA, BK=32, 512
// threads, 32x32 warp tiles). R12 change: SELECTIVE PASS COUNT.
//   - Q/K output tiles (EPI==0, which<2): 3 passes (hh+hl+lh). Q/K errors
//     are softmax-amplified (logit sigma ~64; a 2^-12 drop there = ~1.6%
//     weight error -> fails), so they keep full precision.
//   - V output tiles (EPI==0, which==2): 2 passes. V errors pass through a
//     convex combination -> rel ~2.4e-4.
//   - proj (EPI==1): 2 passes. Dot-product error ~2^-12 ~= 2.4e-4.
// Combined with flash's 2.1e-4 in quadrature: ~4e-4 total, 2.5x margin.
// ===========================================================================
#define GEMM_STAGE_BYTES 32768
#define GEMM_SMEM_BYTES  (2*GEMM_STAGE_BYTES)   // 64 KB

template<int EPI>
__global__ __launch_bounds__(512) void mma_gemm_kernel(
    const float* __restrict__ Ain,
    const float* __restrict__ W,
    const float* __restrict__ bias,
    float* __restrict__ out,
    int K, int Nfull)
{
    extern __shared__ char dsmem[];
    const float* A = (EPI == 1) ? (const float*)g_ctx : Ain;

    const int tid  = threadIdx.x;
    const int wid  = tid >> 5;
    const int lane = tid & 31;
    const int wm   = wid & 3;
    const int wn   = wid >> 2;
    const int gr   = lane >> 2;
    const int tg   = lane & 3;
    const int m0   = blockIdx.y * 128;
    const int n0   = blockIdx.x * 128;

    // third (a_lo x b_hi) pass only where the error budget requires it:
    // Q/K tiles of the QKV GEMM. V tiles and proj run 2-pass.
    const bool pass3 = (EPI == 0) && ((n0 >> 10) != 2);

    const float *pA[2], *pB[2];
    int offA[2], offB[2];
    #pragma unroll
    for (int t = 0; t < 2; t++) {
        int idx = tid + t * 512;
        int row = idx >> 3;
        int c4  = idx & 7;
        pA[t] = A + (size_t)(m0 + row) * K + c4 * 4;
        pB[t] = W + (size_t)(n0 + row) * K + c4 * 4;
        int kk  = c4 >> 2;
        int kw4 = c4 & 3;
        int aih = kw4 >> 1;
        int tg0 = (kw4 & 1) * 2;
        int mt = row >> 4, rw = row & 15;
        int ai = (rw >> 3) | (aih << 1);
        offA[t] = (((kk*8 + mt)*4 + ai) << 5) + (rw & 7)*4 + tg0;
        int nt = row >> 3;
        offB[t] = (((kk*16 + nt)*2 + aih) << 5) + (row & 7)*4 + tg0;
    }

    float acc[2][4][4];
    #pragma unroll
    for (int i = 0; i < 2; i++)
        #pragma unroll
        for (int j = 0; j < 4; j++)
            #pragma unroll
            for (int v = 0; v < 4; v++) acc[i][j][v] = 0.f;

    float4 gA[2], gB[2];
    #pragma unroll
    for (int t = 0; t < 2; t++) {
        gA[t] = *(const float4*)(pA[t]);
        gB[t] = *(const float4*)(pB[t]);
    }
    {
        uint2* sA0 = (uint2*)(dsmem);
        uint2* sB0 = (uint2*)(dsmem + 16384);
        #pragma unroll
        for (int t = 0; t < 2; t++) {
            *(uint4*)(sA0 + offA[t]) = split4(gA[t]);
            *(uint4*)(sB0 + offB[t]) = split4(gB[t]);
        }
    }
    __syncthreads();

    const int niter = K >> 5;
    for (int it = 0; it < niter; it++) {
        const int p = it & 1;
        uint2* cA = (uint2*)(dsmem + p*GEMM_STAGE_BYTES);
        uint2* cB = (uint2*)(dsmem + p*GEMM_STAGE_BYTES + 16384);
        const bool more = (it + 1 < niter);

        if (more) {
            const int ko = (it + 1) << 5;
            #pragma unroll
            for (int t = 0; t < 2; t++) {
                gA[t] = *(const float4*)(pA[t] + ko);
                gB[t] = *(const float4*)(pB[t] + ko);
            }
        }

        #pragma unroll
        for (int kk = 0; kk < 2; kk++) {
            uint32_t ah[2][4], al[2][4], bh[4][2], bl[4][2];
            #pragma unroll
            for (int mt4 = 0; mt4 < 2; mt4++) {
                int mt = wm*2 + mt4;
                #pragma unroll
                for (int ai = 0; ai < 4; ai++) {
                    uint2 v = cA[(((kk*8 + mt)*4 + ai) << 5) + lane];
                    ah[mt4][ai] = v.x;
                    al[mt4][ai] = v.y;
                }
            }
            #pragma unroll
            for (int nt4 = 0; nt4 < 4; nt4++) {
                int nt = wn*4 + nt4;
                #pragma unroll
                for (int bi = 0; bi < 2; bi++) {
                    uint2 v = cB[(((kk*16 + nt)*2 + bi) << 5) + lane];
                    bh[nt4][bi] = v.x;
                    bl[nt4][bi] = v.y;
                }
            }
            #pragma unroll
            for (int mt4 = 0; mt4 < 2; mt4++)
                #pragma unroll
                for (int nt4 = 0; nt4 < 4; nt4++)
                    mma16(acc[mt4][nt4], ah[mt4], bh[nt4]);
            #pragma unroll
            for (int mt4 = 0; mt4 < 2; mt4++)
                #pragma unroll
                for (int nt4 = 0; nt4 < 4; nt4++)
                    mma16(acc[mt4][nt4], ah[mt4], bl[nt4]);
            if (pass3) {
                #pragma unroll
                for (int mt4 = 0; mt4 < 2; mt4++)
                    #pragma unroll
                    for (int nt4 = 0; nt4 < 4; nt4++)
                        mma16(acc[mt4][nt4], al[mt4], bh[nt4]);
            }
        }

        if (more) {
            uint2* nA = (uint2*)(dsmem + (p^1)*GEMM_STAGE_BYTES);
            uint2* nB = (uint2*)(dsmem + (p^1)*GEMM_STAGE_BYTES + 16384);
            #pragma unroll
            for (int t = 0; t < 2; t++) {
                *(uint4*)(nA + offA[t]) = split4(gA[t]);
                *(uint4*)(nB + offB[t]) = split4(gB[t]);
            }
        }
        __syncthreads();
    }

    #pragma unroll
    for (int mt4 = 0; mt4 < 2; mt4++) {
        const int mlo = m0 + wm*32 + mt4*16 + gr;
        const int mhi = mlo + 8;
        #pragma unroll
        for (int nt4 = 0; nt4 < 4; nt4++) {
            const int nn = n0 + wn*32 + nt4*8 + tg*2;
            const float* d = acc[mt4][nt4];
            if (EPI == 0) {
                const int which = n0 >> 10;
                float* dst = (which == 0) ? g_q : ((which == 1) ? g_k : g_v);
                const int nl = nn & 1023;
                const int h  = nl >> 6;
                const int dd = nl & (HDIM - 1);
                {
                    int b = mlo >> 11, s = mlo & (SEQ - 1);
                    *(float2*)&dst[(((b*NHEAD + h)*SEQ) + s)*HDIM + dd] =
                        make_float2(d[0], d[1]);
                }
                {
                    int b = mhi >> 11, s = mhi & (SEQ - 1);
                    *(float2*)&dst[(((b*NHEAD + h)*SEQ) + s)*HDIM + dd] =
                        make_float2(d[2], d[3]);
                }
            } else {
                float2 bv = *(const float2*)&bias[nn];
                *(float2*)&out[(size_t)mlo * Nfull + nn] =
                    make_float2(d[0] + bv.x, d[1] + bv.y);
                *(float2*)&out[(size_t)mhi * Nfull + nn] =
                    make_float2(d[2] + bv.x, d[3] + bv.y);
            }
        }
    }
}

// ===========================================================================
// Causal flash attention on tensor cores — R11 winner, unchanged:
// 3-pass S (softmax-amplified), 2-pass PV, V stored hi-only.
// ===========================================================================
#define FLASH_SMEM_BYTES 57344   // Q 32K + K 16K + V 8K

__global__ __launch_bounds__(256) void flash_mma_kernel()
{
    extern __shared__ char fsm[];
    uint2*    sQ = (uint2*)(fsm);              // 4096 uint2
    uint2*    sK = (uint2*)(fsm + 32768);      // 2048 uint2
    uint32_t* sV = (uint32_t*)(fsm + 49152);   // 2048 uint32 (hi only)

    const int qt = blockIdx.x;
    const int h  = blockIdx.y;
    const int b  = blockIdx.z;
    const int bh = b*NHEAD + h;
    const float* Qg = g_q + (size_t)bh * SEQ * HDIM;
    const float* Kg = g_k + (size_t)bh * SEQ * HDIM;
    const float* Vg = g_v + (size_t)bh * SEQ * HDIM;

    const int tid  = threadIdx.x;
    const int w    = tid >> 5;
    const int lane = tid & 31;
    const int gr   = lane >> 2;
    const int tg   = lane & 3;
    const int q0   = qt * 128;

    // ---- fill Q fragments once (x8 scale folded) ----
    #pragma unroll
    for (int t = 0; t < 8; t++) {
        int idx = tid + t * 256;       // 0..2047 float4 slots
        int row = idx >> 4;            // 0..127
        int c4  = idx & 15;
        float4 v = *(const float4*)(Qg + (size_t)(q0 + row)*HDIM + c4*4);
        v.x *= 8.f; v.y *= 8.f; v.z *= 8.f; v.w *= 8.f;
        int kk  = c4 >> 2;
        int kw4 = c4 & 3;
        int aih = kw4 >> 1;
        int tg0 = (kw4 & 1) * 2;
        int mt = row >> 4, rw = row & 15;
        int ai = (rw >> 3) | (aih << 1);
        *(uint4*)(sQ + (((kk*8 + mt)*4 + ai) << 5) + (rw & 7)*4 + tg0) = split4(v);
    }

    float m0 = -1e30f, m1 = -1e30f, l0 = 0.f, l1 = 0.f;
    float cacc[8][4];
    #pragma unroll
    for (int nt = 0; nt < 8; nt++)
        #pragma unroll
        for (int v = 0; v < 4; v++) cacc[nt][v] = 0.f;

    const int qrow0 = q0 + 16*w + gr;   // thread's low row
    const int nkt   = 2*qt + 2;         // causal kv-tile count

    for (int kt = 0; kt < nkt; kt++) {
        const int k0 = kt * 64;
        __syncthreads();   // previous iteration's mma reads complete

        // ---- fill K fragments: B-operand (k=d, n=key), (hi,lo) ----
        #pragma unroll
        for (int t = 0; t < 4; t++) {
            int idx = tid + t * 256;   // 0..1023
            int row = idx >> 4;        // key 0..63
            int c4  = idx & 15;
            float4 v = *(const float4*)(Kg + (size_t)(k0 + row)*HDIM + c4*4);
            int kk  = c4 >> 2;
            int kw4 = c4 & 3;
            int bi  = kw4 >> 1;
            int tg0 = (kw4 & 1) * 2;
            int nt  = row >> 3;
            *(uint4*)(sK + (((kk*8 + nt)*2 + bi) << 5) + (row & 7)*4 + tg0) = split4(v);
        }

        // ---- fill V fragments: B-operand (k=key, n=d), HI ONLY ----
        #pragma unroll
        for (int t = 0; t < 2; t++) {
            int idx = tid + t * 256;   // 0..511
            int kp  = idx >> 4;        // key pair 0..31
            int c4  = idx & 15;        // d/4
            float4 v0 = *(const float4*)(Vg + (size_t)(k0 + 2*kp  )*HDIM + c4*4);
            float4 v1 = *(const float4*)(Vg + (size_t)(k0 + 2*kp+1)*HDIM + c4*4);
            int kkv = kp >> 3;
            int tgp = kp & 7;
            int bi  = tgp >> 2;
            int tgv = tgp & 3;
            const float a0[4] = {v0.x, v0.y, v0.z, v0.w};
            const float a1[4] = {v1.x, v1.y, v1.z, v1.w};
            #pragma unroll
            for (int j = 0; j < 4; j++) {
                int d  = c4*4 + j;
                int nt = d >> 3;
                int grv = d & 7;
                __half2 hh = __floats2half2_rn(a0[j], a1[j]);
                int ln = (grv*4 + tgv) ^ ((nt & 3) << 2);   // bank swizzle
                sV[(((kkv*8 + nt)*2 + bi) << 5) + ln] =
                    *reinterpret_cast<uint32_t*>(&hh);
            }
        }
        __syncthreads();

        // warps whose rows are entirely left of this kv tile: skip compute
        if (k0 <= q0 + 16*w + 15) {
            // ---- S = (16q) @ K^T via 3xFP16 ----
            float sacc[8][4];
            #pragma unroll
            for (int nt = 0; nt < 8; nt++)
                #pragma unroll
                for (int v = 0; v < 4; v++) sacc[nt][v] = 0.f;

            #pragma unroll
            for (int kk = 0; kk < 4; kk++) {
                uint32_t qh[4], ql[4], kh[8][2], kl[8][2];
                #pragma unroll
                for (int ai = 0; ai < 4; ai++) {
                    uint2 v = sQ[(((kk*8 + w)*4 + ai) << 5) + lane];
                    qh[ai] = v.x; ql[ai] = v.y;
                }
                #pragma unroll
                for (int nt = 0; nt < 8; nt++)
                    #pragma unroll
                    for (int bi = 0; bi < 2; bi++) {
                        uint2 v = sK[(((kk*8 + nt)*2 + bi) << 5) + lane];
                        kh[nt][bi] = v.x; kl[nt][bi] = v.y;
                    }
                #pragma unroll
                for (int nt = 0; nt < 8; nt++) mma16(sacc[nt], qh, kh[nt]);
                #pragma unroll
                for (int nt = 0; nt < 8; nt++) mma16(sacc[nt], qh, kl[nt]);
                #pragma unroll
                for (int nt = 0; nt < 8; nt++) mma16(sacc[nt], ql, kh[nt]);
            }

            // ---- causal mask (diagonal region only) ----
            if (k0 + 63 > qrow0 || k0 + 63 > qrow0 + 8) {
                #pragma unroll
                for (int nt = 0; nt < 8; nt++) {
                    int c = k0 + nt*8 + 2*tg;
                    if (c     > qrow0    ) sacc[nt][0] = -1e30f;
                    if (c + 1 > qrow0    ) sacc[nt][1] = -1e30f;
                    if (c     > qrow0 + 8) sacc[nt][2] = -1e30f;
                    if (c + 1 > qrow0 + 8) sacc[nt][3] = -1e30f;
                }
            }

            // ---- online softmax (rows gr, gr+8; reduce over 4 tg lanes) ----
            float mx0 = -1e30f, mx1 = -1e30f;
            #pragma unroll
            for (int nt = 0; nt < 8; nt++) {
                mx0 = fmaxf(mx0, fmaxf(sacc[nt][0], sacc[nt][1]));
                mx1 = fmaxf(mx1, fmaxf(sacc[nt][2], sacc[nt][3]));
            }
            mx0 = fmaxf(mx0, __shfl_xor_sync(0xffffffffu, mx0, 1));
            mx0 = fmaxf(mx0, __shfl_xor_sync(0xffffffffu, mx0, 2));
            mx1 = fmaxf(mx1, __shfl_xor_sync(0xffffffffu, mx1, 1));
            mx1 = fmaxf(mx1, __shfl_xor_sync(0xffffffffu, mx1, 2));
            float mn0 = fmaxf(m0, mx0), mn1 = fmaxf(m1, mx1);
            float al0 = __expf(m0 - mn0), al1 = __expf(m1 - mn1);
            m0 = mn0; m1 = mn1;

            float rs0 = 0.f, rs1 = 0.f;
            #pragma unroll
            for (int nt = 0; nt < 8; nt++) {
                sacc[nt][0] = __expf(sacc[nt][0] - mn0); rs0 += sacc[nt][0];
                sacc[nt][1] = __expf(sacc[nt][1] - mn0); rs0 += sacc[nt][1];
                sacc[nt][2] = __expf(sacc[nt][2] - mn1); rs1 += sacc[nt][2];
                sacc[nt][3] = __expf(sacc[nt][3] - mn1); rs1 += sacc[nt][3];
            }
            rs0 += __shfl_xor_sync(0xffffffffu, rs0, 1);
            rs0 += __shfl_xor_sync(0xffffffffu, rs0, 2);
            rs1 += __shfl_xor_sync(0xffffffffu, rs1, 1);
            rs1 += __shfl_xor_sync(0xffffffffu, rs1, 2);
            l0 = l0 * al0 + rs0;
            l1 = l1 * al1 + rs1;

            #pragma unroll
            for (int nt = 0; nt < 8; nt++) {
                cacc[nt][0] *= al0; cacc[nt][1] *= al0;
                cacc[nt][2] *= al1; cacc[nt][3] *= al1;
            }

            // ---- PV (2-pass): P (hi,lo) from registers x V hi ----
            #pragma unroll
            for (int kkv = 0; kkv < 4; kkv++) {
                uint32_t ph[4], pl[4], vh[8][2];
                pack_hl(sacc[2*kkv  ][0], sacc[2*kkv  ][1], ph[0], pl[0]);
                pack_hl(sacc[2*kkv  ][2], sacc[2*kkv  ][3], ph[1], pl[1]);
                pack_hl(sacc[2*kkv+1][0], sacc[2*kkv+1][1], ph[2], pl[2]);
                pack_hl(sacc[2*kkv+1][2], sacc[2*kkv+1][3], ph[3], pl[3]);
                #pragma unroll
                for (int nt = 0; nt < 8; nt++) {
                    int ln = lane ^ ((nt & 3) << 2);
                    #pragma unroll
                    for (int bi = 0; bi < 2; bi++)
                        vh[nt][bi] = sV[(((kkv*8 + nt)*2 + bi) << 5) + ln];
                }
                #pragma unroll
                for (int nt = 0; nt < 8; nt++) mma16(cacc[nt], ph, vh[nt]);
                #pragma unroll
                for (int nt = 0; nt < 8; nt++) mma16(cacc[nt], pl, vh[nt]);
            }
        }
    }

    // ---- epilogue: ctx[b][s][h*64+d] = acc / l ----
    const float inv0 = 1.0f / l0;
    const float inv1 = 1.0f / l1;
    float* o0 = g_ctx + ((size_t)(b*SEQ + qrow0    )) * EMB + h*HDIM;
    float* o1 = g_ctx + ((size_t)(b*SEQ + qrow0 + 8)) * EMB + h*HDIM;
    #pragma unroll
    for (int nt = 0; nt < 8; nt++) {
        int d = nt*8 + 2*tg;
        *(float2*)(o0 + d) = make_float2(cacc[nt][0]*inv0, cacc[nt][1]*inv0);
        *(float2*)(o1 + d) = make_float2(cacc[nt][2]*inv1, cacc[nt][3]*inv1);
    }
}

// ---------------------------------------------------------------------------
// Inputs (metadata order): x [2,2048,1024] f32, w_qkv [3072,1024] f32,
// w_proj [1024,1024] f32, b_proj [1024] f32. Output: [2,2048,1024] f32.
// ---------------------------------------------------------------------------
extern "C" void kernel_launch(void* const* d_in, const int* in_sizes, int n_in,
                              void* d_out, int out_size)
{
    (void)in_sizes; (void)n_in; (void)out_size;
    const float* x      = (const float*)d_in[0];
    const float* w_qkv  = (const float*)d_in[1];
    const float* w_proj = (const float*)d_in[2];
    const float* b_proj = (const float*)d_in[3];
    float* out = (float*)d_out;

    cudaFuncSetAttribute(mma_gemm_kernel<0>,
                         cudaFuncAttributeMaxDynamicSharedMemorySize, GEMM_SMEM_BYTES);
    cudaFuncSetAttribute(mma_gemm_kernel<1>,
                         cudaFuncAttributeMaxDynamicSharedMemorySize, GEMM_SMEM_BYTES);
    cudaFuncSetAttribute(flash_mma_kernel,
                         cudaFuncAttributeMaxDynamicSharedMemorySize, FLASH_SMEM_BYTES);

    // 1) QKV GEMM (3-pass Q/K, 2-pass V): -> g_q/g_k/g_v
    dim3 g1((3*EMB)/128, MTOT/128);
    mma_gemm_kernel<0><<<g1, 512, GEMM_SMEM_BYTES>>>(x, w_qkv, nullptr, nullptr,
                                                     EMB, 3*EMB);

    // 2) Causal flash attention (3-pass S, 2-pass PV) -> g_ctx
    dim3 g2(SEQ/128, NHEAD, BATCH);
    flash_mma_kernel<<<g2, 256, FLASH_SMEM_BYTES>>>();

    // 3) Proj GEMM + bias (2-pass): g_ctx @ w_proj^T + b_proj -> out
    dim3 g3(EMB/128, MTOT/128);
    mma_gemm_kernel<1><<<g3, 512, GEMM_SMEM_BYTES>>>(nullptr, w_proj, b_proj, out,
                                                     EMB, EMB);
}

// round 14
// speedup vs baseline: 1.2093x; 1.0499x over previous
#include <cuda_runtime.h>
#include <cuda_fp16.h>
#include <math.h>
#include <stdint.h>

#define BATCH 2
#define SEQ   2048
#define EMB   1024
#define NHEAD 16
#define HDIM  64
#define MTOT  (BATCH*SEQ)   // 4096

// Scratch (allocation-free contract: __device__ globals)
__device__ float g_q[BATCH*NHEAD*SEQ*HDIM];   // [b][h][s][d]
__device__ float g_k[BATCH*NHEAD*SEQ*HDIM];
__device__ float g_v[BATCH*NHEAD*SEQ*HDIM];
__device__ float g_ctx[(size_t)MTOT*EMB];     // [b*s][e]

// ===========================================================================
// m16n8k16 fp16 mma.sync, fp32 accumulate. Calibrated R5-R12: the sm_103
// legacy-HMMA path runs at a FIXED ~0.174 warp-mma/cyc/SM — wall time is
// proportional to mma instruction count; pass-count reduction within the
// 1e-3 error budget is THE lever, and it only pays when applied uniformly
// to a launch (heterogeneous cuts hide in SM-level slack, per R12).
// ===========================================================================
__device__ __forceinline__ void mma16(float* d, const uint32_t* a, const uint32_t* b) {
    asm volatile(
        "mma.sync.aligned.m16n8k16.row.col.f32.f16.f16.f32 "
        "{%0,%1,%2,%3}, {%4,%5,%6,%7}, {%8,%9}, {%0,%1,%2,%3};"
        : "+f"(d[0]), "+f"(d[1]), "+f"(d[2]), "+f"(d[3])
        : "r"(a[0]), "r"(a[1]), "r"(a[2]), "r"(a[3]), "r"(b[0]), "r"(b[1]));
}

// Split float4 into fp16 (hi, lo) pair-packed b32 words.
__device__ __forceinline__ uint4 split4(float4 g) {
    __half2 h01 = __floats2half2_rn(g.x, g.y);
    __half2 h23 = __floats2half2_rn(g.z, g.w);
    float2 f01 = __half22float2(h01);
    float2 f23 = __half22float2(h23);
    __half2 l01 = __floats2half2_rn(g.x - f01.x, g.y - f01.y);
    __half2 l23 = __floats2half2_rn(g.z - f23.x, g.w - f23.y);
    uint4 r;
    r.x = *reinterpret_cast<uint32_t*>(&h01);
    r.y = *reinterpret_cast<uint32_t*>(&l01);
    r.z = *reinterpret_cast<uint32_t*>(&h23);
    r.w = *reinterpret_cast<uint32_t*>(&l23);
    return r;
}

// ===========================================================================
// FP16 mma.sync GEMM, double-buffered (R9 config: 128x128 CTA, BK=32, 512
// threads, 32x32 warp tiles). R13 pass policy (uniform per launch where
// possible):
//   - QKV (EPI==0): Q/K tiles 3-pass (softmax-amplified, mandatory);
//     V tiles 2-pass.
//   - proj (EPI==1): 1-PASS (hh only). Dot error ~sqrt(2)*2^-11 ~= 6.9e-4
//     component; fits the budget. Halves proj mma AND skips lo loads.
// ===========================================================================
#define GEMM_STAGE_BYTES 32768
#define GEMM_SMEM_BYTES  (2*GEMM_STAGE_BYTES)   // 64 KB

template<int EPI>
__global__ __launch_bounds__(512) void mma_gemm_kernel(
    const float* __restrict__ Ain,
    const float* __restrict__ W,
    const float* __restrict__ bias,
    float* __restrict__ out,
    int K, int Nfull)
{
    extern __shared__ char dsmem[];
    const float* A = (EPI == 1) ? (const float*)g_ctx : Ain;

    const int tid  = threadIdx.x;
    const int wid  = tid >> 5;
    const int lane = tid & 31;
    const int wm   = wid & 3;
    const int wn   = wid >> 2;
    const int gr   = lane >> 2;
    const int tg   = lane & 3;
    const int m0   = blockIdx.y * 128;
    const int n0   = blockIdx.x * 128;

    const bool pass2 = (EPI == 0);                            // proj: 1-pass
    const bool pass3 = (EPI == 0) && ((n0 >> 10) != 2);       // Q/K: 3-pass

    const float *pA[2], *pB[2];
    int offA[2], offB[2];
    #pragma unroll
    for (int t = 0; t < 2; t++) {
        int idx = tid + t * 512;
        int row = idx >> 3;
        int c4  = idx & 7;
        pA[t] = A + (size_t)(m0 + row) * K + c4 * 4;
        pB[t] = W + (size_t)(n0 + row) * K + c4 * 4;
        int kk  = c4 >> 2;
        int kw4 = c4 & 3;
        int aih = kw4 >> 1;
        int tg0 = (kw4 & 1) * 2;
        int mt = row >> 4, rw = row & 15;
        int ai = (rw >> 3) | (aih << 1);
        offA[t] = (((kk*8 + mt)*4 + ai) << 5) + (rw & 7)*4 + tg0;
        int nt = row >> 3;
        offB[t] = (((kk*16 + nt)*2 + aih) << 5) + (row & 7)*4 + tg0;
    }

    float acc[2][4][4];
    #pragma unroll
    for (int i = 0; i < 2; i++)
        #pragma unroll
        for (int j = 0; j < 4; j++)
            #pragma unroll
            for (int v = 0; v < 4; v++) acc[i][j][v] = 0.f;

    float4 gA[2], gB[2];
    #pragma unroll
    for (int t = 0; t < 2; t++) {
        gA[t] = *(const float4*)(pA[t]);
        gB[t] = *(const float4*)(pB[t]);
    }
    {
        uint2* sA0 = (uint2*)(dsmem);
        uint2* sB0 = (uint2*)(dsmem + 16384);
        #pragma unroll
        for (int t = 0; t < 2; t++) {
            *(uint4*)(sA0 + offA[t]) = split4(gA[t]);
            *(uint4*)(sB0 + offB[t]) = split4(gB[t]);
        }
    }
    __syncthreads();

    const int niter = K >> 5;
    for (int it = 0; it < niter; it++) {
        const int p = it & 1;
        uint2* cA = (uint2*)(dsmem + p*GEMM_STAGE_BYTES);
        uint2* cB = (uint2*)(dsmem + p*GEMM_STAGE_BYTES + 16384);
        const bool more = (it + 1 < niter);

        if (more) {
            const int ko = (it + 1) << 5;
            #pragma unroll
            for (int t = 0; t < 2; t++) {
                gA[t] = *(const float4*)(pA[t] + ko);
                gB[t] = *(const float4*)(pB[t] + ko);
            }
        }

        #pragma unroll
        for (int kk = 0; kk < 2; kk++) {
            uint32_t ah[2][4], al[2][4], bh[4][2], bl[4][2];
            #pragma unroll
            for (int mt4 = 0; mt4 < 2; mt4++) {
                int mt = wm*2 + mt4;
                #pragma unroll
                for (int ai = 0; ai < 4; ai++) {
                    uint2 v = cA[(((kk*8 + mt)*4 + ai) << 5) + lane];
                    ah[mt4][ai] = v.x;
                    al[mt4][ai] = v.y;
                }
            }
            #pragma unroll
            for (int nt4 = 0; nt4 < 4; nt4++) {
                int nt = wn*4 + nt4;
                #pragma unroll
                for (int bi = 0; bi < 2; bi++) {
                    uint2 v = cB[(((kk*16 + nt)*2 + bi) << 5) + lane];
                    bh[nt4][bi] = v.x;
                    bl[nt4][bi] = v.y;
                }
            }
            #pragma unroll
            for (int mt4 = 0; mt4 < 2; mt4++)
                #pragma unroll
                for (int nt4 = 0; nt4 < 4; nt4++)
                    mma16(acc[mt4][nt4], ah[mt4], bh[nt4]);
            if (pass2) {
                #pragma unroll
                for (int mt4 = 0; mt4 < 2; mt4++)
                    #pragma unroll
                    for (int nt4 = 0; nt4 < 4; nt4++)
                        mma16(acc[mt4][nt4], ah[mt4], bl[nt4]);
            }
            if (pass3) {
                #pragma unroll
                for (int mt4 = 0; mt4 < 2; mt4++)
                    #pragma unroll
                    for (int nt4 = 0; nt4 < 4; nt4++)
                        mma16(acc[mt4][nt4], al[mt4], bh[nt4]);
            }
        }

        if (more) {
            uint2* nA = (uint2*)(dsmem + (p^1)*GEMM_STAGE_BYTES);
            uint2* nB = (uint2*)(dsmem + (p^1)*GEMM_STAGE_BYTES + 16384);
            #pragma unroll
            for (int t = 0; t < 2; t++) {
                *(uint4*)(nA + offA[t]) = split4(gA[t]);
                *(uint4*)(nB + offB[t]) = split4(gB[t]);
            }
        }
        __syncthreads();
    }

    #pragma unroll
    for (int mt4 = 0; mt4 < 2; mt4++) {
        const int mlo = m0 + wm*32 + mt4*16 + gr;
        const int mhi = mlo + 8;
        #pragma unroll
        for (int nt4 = 0; nt4 < 4; nt4++) {
            const int nn = n0 + wn*32 + nt4*8 + tg*2;
            const float* d = acc[mt4][nt4];
            if (EPI == 0) {
                const int which = n0 >> 10;
                float* dst = (which == 0) ? g_q : ((which == 1) ? g_k : g_v);
                const int nl = nn & 1023;
                const int h  = nl >> 6;
                const int dd = nl & (HDIM - 1);
                {
                    int b = mlo >> 11, s = mlo & (SEQ - 1);
                    *(float2*)&dst[(((b*NHEAD + h)*SEQ) + s)*HDIM + dd] =
                        make_float2(d[0], d[1]);
                }
                {
                    int b = mhi >> 11, s = mhi & (SEQ - 1);
                    *(float2*)&dst[(((b*NHEAD + h)*SEQ) + s)*HDIM + dd] =
                        make_float2(d[2], d[3]);
                }
            } else {
                float2 bv = *(const float2*)&bias[nn];
                *(float2*)&out[(size_t)mlo * Nfull + nn] =
                    make_float2(d[0] + bv.x, d[1] + bv.y);
                *(float2*)&out[(size_t)mhi * Nfull + nn] =
                    make_float2(d[2] + bv.x, d[3] + bv.y);
            }
        }
    }
}

// ===========================================================================
// Causal flash attention on tensor cores. R13 changes:
//   - PV is 1-PASS: ph x vh only (dropped pl pass adds ~2.8e-4 on weights;
//     V-lo already dropped in R11). Cuts flash mma 22% and halves the pack
//     ALU in the hot loop.
//   - LPT launch order: qt = gridDim.x-1-blockIdx.x so the 32-tile blocks
//     start first and 2-tile blocks drain the scheduling tail.
// 3-pass S unchanged (softmax-amplified; mandatory).
// ===========================================================================
#define FLASH_SMEM_BYTES 57344   // Q 32K + K 16K + V 8K

__global__ __launch_bounds__(256) void flash_mma_kernel()
{
    extern __shared__ char fsm[];
    uint2*    sQ = (uint2*)(fsm);              // 4096 uint2
    uint2*    sK = (uint2*)(fsm + 32768);      // 2048 uint2
    uint32_t* sV = (uint32_t*)(fsm + 49152);   // 2048 uint32 (hi only)

    const int qt = (gridDim.x - 1) - blockIdx.x;   // LPT: heavy blocks first
    const int h  = blockIdx.y;
    const int b  = blockIdx.z;
    const int bh = b*NHEAD + h;
    const float* Qg = g_q + (size_t)bh * SEQ * HDIM;
    const float* Kg = g_k + (size_t)bh * SEQ * HDIM;
    const float* Vg = g_v + (size_t)bh * SEQ * HDIM;

    const int tid  = threadIdx.x;
    const int w    = tid >> 5;
    const int lane = tid & 31;
    const int gr   = lane >> 2;
    const int tg   = lane & 3;
    const int q0   = qt * 128;

    // ---- fill Q fragments once (x8 scale folded) ----
    #pragma unroll
    for (int t = 0; t < 8; t++) {
        int idx = tid + t * 256;       // 0..2047 float4 slots
        int row = idx >> 4;            // 0..127
        int c4  = idx & 15;
        float4 v = *(const float4*)(Qg + (size_t)(q0 + row)*HDIM + c4*4);
        v.x *= 8.f; v.y *= 8.f; v.z *= 8.f; v.w *= 8.f;
        int kk  = c4 >> 2;
        int kw4 = c4 & 3;
        int aih = kw4 >> 1;
        int tg0 = (kw4 & 1) * 2;
        int mt = row >> 4, rw = row & 15;
        int ai = (rw >> 3) | (aih << 1);
        *(uint4*)(sQ + (((kk*8 + mt)*4 + ai) << 5) + (rw & 7)*4 + tg0) = split4(v);
    }

    float m0 = -1e30f, m1 = -1e30f, l0 = 0.f, l1 = 0.f;
    float cacc[8][4];
    #pragma unroll
    for (int nt = 0; nt < 8; nt++)
        #pragma unroll
        for (int v = 0; v < 4; v++) cacc[nt][v] = 0.f;

    const int qrow0 = q0 + 16*w + gr;   // thread's low row
    const int nkt   = 2*qt + 2;         // causal kv-tile count

    for (int kt = 0; kt < nkt; kt++) {
        const int k0 = kt * 64;
        __syncthreads();   // previous iteration's mma reads complete

        // ---- fill K fragments: B-operand (k=d, n=key), (hi,lo) ----
        #pragma unroll
        for (int t = 0; t < 4; t++) {
            int idx = tid + t * 256;   // 0..1023
            int row = idx >> 4;        // key 0..63
            int c4  = idx & 15;
            float4 v = *(const float4*)(Kg + (size_t)(k0 + row)*HDIM + c4*4);
            int kk  = c4 >> 2;
            int kw4 = c4 & 3;
            int bi  = kw4 >> 1;
            int tg0 = (kw4 & 1) * 2;
            int nt  = row >> 3;
            *(uint4*)(sK + (((kk*8 + nt)*2 + bi) << 5) + (row & 7)*4 + tg0) = split4(v);
        }

        // ---- fill V fragments: B-operand (k=key, n=d), HI ONLY ----
        #pragma unroll
        for (int t = 0; t < 2; t++) {
            int idx = tid + t * 256;   // 0..511
            int kp  = idx >> 4;        // key pair 0..31
            int c4  = idx & 15;        // d/4
            float4 v0 = *(const float4*)(Vg + (size_t)(k0 + 2*kp  )*HDIM + c4*4);
            float4 v1 = *(const float4*)(Vg + (size_t)(k0 + 2*kp+1)*HDIM + c4*4);
            int kkv = kp >> 3;
            int tgp = kp & 7;
            int bi  = tgp >> 2;
            int tgv = tgp & 3;
            const float a0[4] = {v0.x, v0.y, v0.z, v0.w};
            const float a1[4] = {v1.x, v1.y, v1.z, v1.w};
            #pragma unroll
            for (int j = 0; j < 4; j++) {
                int d  = c4*4 + j;
                int nt = d >> 3;
                int grv = d & 7;
                __half2 hh = __floats2half2_rn(a0[j], a1[j]);
                int ln = (grv*4 + tgv) ^ ((nt & 3) << 2);   // bank swizzle
                sV[(((kkv*8 + nt)*2 + bi) << 5) + ln] =
                    *reinterpret_cast<uint32_t*>(&hh);
            }
        }
        __syncthreads();

        // warps whose rows are entirely left of this kv tile: skip compute
        if (k0 <= q0 + 16*w + 15) {
            // ---- S = (16q) @ K^T via 3xFP16 ----
            float sacc[8][4];
            #pragma unroll
            for (int nt = 0; nt < 8; nt++)
                #pragma unroll
                for (int v = 0; v < 4; v++) sacc[nt][v] = 0.f;

            #pragma unroll
            for (int kk = 0; kk < 4; kk++) {
                uint32_t qh[4], ql[4], kh[8][2], kl[8][2];
                #pragma unroll
                for (int ai = 0; ai < 4; ai++) {
                    uint2 v = sQ[(((kk*8 + w)*4 + ai) << 5) + lane];
                    qh[ai] = v.x; ql[ai] = v.y;
                }
                #pragma unroll
                for (int nt = 0; nt < 8; nt++)
                    #pragma unroll
                    for (int bi = 0; bi < 2; bi++) {
                        uint2 v = sK[(((kk*8 + nt)*2 + bi) << 5) + lane];
                        kh[nt][bi] = v.x; kl[nt][bi] = v.y;
                    }
                #pragma unroll
                for (int nt = 0; nt < 8; nt++) mma16(sacc[nt], qh, kh[nt]);
                #pragma unroll
                for (int nt = 0; nt < 8; nt++) mma16(sacc[nt], qh, kl[nt]);
                #pragma unroll
                for (int nt = 0; nt < 8; nt++) mma16(sacc[nt], ql, kh[nt]);
            }

            // ---- causal mask (diagonal region only) ----
            if (k0 + 63 > qrow0 || k0 + 63 > qrow0 + 8) {
                #pragma unroll
                for (int nt = 0; nt < 8; nt++) {
                    int c = k0 + nt*8 + 2*tg;
                    if (c     > qrow0    ) sacc[nt][0] = -1e30f;
                    if (c + 1 > qrow0    ) sacc[nt][1] = -1e30f;
                    if (c     > qrow0 + 8) sacc[nt][2] = -1e30f;
                    if (c + 1 > qrow0 + 8) sacc[nt][3] = -1e30f;
                }
            }

            // ---- online softmax (rows gr, gr+8; reduce over 4 tg lanes) ----
            float mx0 = -1e30f, mx1 = -1e30f;
            #pragma unroll
            for (int nt = 0; nt < 8; nt++) {
                mx0 = fmaxf(mx0, fmaxf(sacc[nt][0], sacc[nt][1]));
                mx1 = fmaxf(mx1, fmaxf(sacc[nt][2], sacc[nt][3]));
            }
            mx0 = fmaxf(mx0, __shfl_xor_sync(0xffffffffu, mx0, 1));
            mx0 = fmaxf(mx0, __shfl_xor_sync(0xffffffffu, mx0, 2));
            mx1 = fmaxf(mx1, __shfl_xor_sync(0xffffffffu, mx1, 1));
            mx1 = fmaxf(mx1, __shfl_xor_sync(0xffffffffu, mx1, 2));
            float mn0 = fmaxf(m0, mx0), mn1 = fmaxf(m1, mx1);
            float al0 = __expf(m0 - mn0), al1 = __expf(m1 - mn1);
            m0 = mn0; m1 = mn1;

            float rs0 = 0.f, rs1 = 0.f;
            #pragma unroll
            for (int nt = 0; nt < 8; nt++) {
                sacc[nt][0] = __expf(sacc[nt][0] - mn0); rs0 += sacc[nt][0];
                sacc[nt][1] = __expf(sacc[nt][1] - mn0); rs0 += sacc[nt][1];
                sacc[nt][2] = __expf(sacc[nt][2] - mn1); rs1 += sacc[nt][2];
                sacc[nt][3] = __expf(sacc[nt][3] - mn1); rs1 += sacc[nt][3];
            }
            rs0 += __shfl_xor_sync(0xffffffffu, rs0, 1);
            rs0 += __shfl_xor_sync(0xffffffffu, rs0, 2);
            rs1 += __shfl_xor_sync(0xffffffffu, rs1, 1);
            rs1 += __shfl_xor_sync(0xffffffffu, rs1, 2);
            l0 = l0 * al0 + rs0;
            l1 = l1 * al1 + rs1;

            #pragma unroll
            for (int nt = 0; nt < 8; nt++) {
                cacc[nt][0] *= al0; cacc[nt][1] *= al0;
                cacc[nt][2] *= al1; cacc[nt][3] *= al1;
            }

            // ---- PV (1-pass): P hi from registers x V hi ----
            #pragma unroll
            for (int kkv = 0; kkv < 4; kkv++) {
                uint32_t ph[4], vh[8][2];
                {
                    __half2 h0 = __floats2half2_rn(sacc[2*kkv  ][0], sacc[2*kkv  ][1]);
                    __half2 h1 = __floats2half2_rn(sacc[2*kkv  ][2], sacc[2*kkv  ][3]);
                    __half2 h2 = __floats2half2_rn(sacc[2*kkv+1][0], sacc[2*kkv+1][1]);
                    __half2 h3 = __floats2half2_rn(sacc[2*kkv+1][2], sacc[2*kkv+1][3]);
                    ph[0] = *reinterpret_cast<uint32_t*>(&h0);
                    ph[1] = *reinterpret_cast<uint32_t*>(&h1);
                    ph[2] = *reinterpret_cast<uint32_t*>(&h2);
                    ph[3] = *reinterpret_cast<uint32_t*>(&h3);
                }
                #pragma unroll
                for (int nt = 0; nt < 8; nt++) {
                    int ln = lane ^ ((nt & 3) << 2);
                    #pragma unroll
                    for (int bi = 0; bi < 2; bi++)
                        vh[nt][bi] = sV[(((kkv*8 + nt)*2 + bi) << 5) + ln];
                }
                #pragma unroll
                for (int nt = 0; nt < 8; nt++) mma16(cacc[nt], ph, vh[nt]);
            }
        }
    }

    // ---- epilogue: ctx[b][s][h*64+d] = acc / l ----
    const float inv0 = 1.0f / l0;
    const float inv1 = 1.0f / l1;
    float* o0 = g_ctx + ((size_t)(b*SEQ + qrow0    )) * EMB + h*HDIM;
    float* o1 = g_ctx + ((size_t)(b*SEQ + qrow0 + 8)) * EMB + h*HDIM;
    #pragma unroll
    for (int nt = 0; nt < 8; nt++) {
        int d = nt*8 + 2*tg;
        *(float2*)(o0 + d) = make_float2(cacc[nt][0]*inv0, cacc[nt][1]*inv0);
        *(float2*)(o1 + d) = make_float2(cacc[nt][2]*inv1, cacc[nt][3]*inv1);
    }
}

// ---------------------------------------------------------------------------
// Inputs (metadata order): x [2,2048,1024] f32, w_qkv [3072,1024] f32,
// w_proj [1024,1024] f32, b_proj [1024] f32. Output: [2,2048,1024] f32.
// ---------------------------------------------------------------------------
extern "C" void kernel_launch(void* const* d_in, const int* in_sizes, int n_in,
                              void* d_out, int out_size)
{
    (void)in_sizes; (void)n_in; (void)out_size;
    const float* x      = (const float*)d_in[0];
    const float* w_qkv  = (const float*)d_in[1];
    const float* w_proj = (const float*)d_in[2];
    const float* b_proj = (const float*)d_in[3];
    float* out = (float*)d_out;

    cudaFuncSetAttribute(mma_gemm_kernel<0>,
                         cudaFuncAttributeMaxDynamicSharedMemorySize, GEMM_SMEM_BYTES);
    cudaFuncSetAttribute(mma_gemm_kernel<1>,
                         cudaFuncAttributeMaxDynamicSharedMemorySize, GEMM_SMEM_BYTES);
    cudaFuncSetAttribute(flash_mma_kernel,
                         cudaFuncAttributeMaxDynamicSharedMemorySize, FLASH_SMEM_BYTES);

    // 1) QKV GEMM (3-pass Q/K, 2-pass V): -> g_q/g_k/g_v
    dim3 g1((3*EMB)/128, MTOT/128);
    mma_gemm_kernel<0><<<g1, 512, GEMM_SMEM_BYTES>>>(x, w_qkv, nullptr, nullptr,
                                                     EMB, 3*EMB);

    // 2) Causal flash attention (3-pass S, 1-pass PV, LPT order) -> g_ctx
    dim3 g2(SEQ/128, NHEAD, BATCH);
    flash_mma_kernel<<<g2, 256, FLASH_SMEM_BYTES>>>();

    // 3) Proj GEMM + bias (1-pass): g_ctx @ w_proj^T + b_proj -> out
    dim3 g3(EMB/128, MTOT/128);
    mma_gemm_kernel<1><<<g3, 512, GEMM_SMEM_BYTES>>>(nullptr, w_proj, b_proj, out,
                                                     EMB, EMB);
}

// round 15
// speedup vs baseline: 1.2674x; 1.0480x over previous
#include <cuda_runtime.h>
#include <cuda_fp16.h>
#include <math.h>
#include <stdint.h>

#define BATCH 2
#define SEQ   2048
#define EMB   1024
#define NHEAD 16
#define HDIM  64
#define MTOT  (BATCH*SEQ)   // 4096

// Scratch (allocation-free contract: __device__ globals)
__device__ float g_q[BATCH*NHEAD*SEQ*HDIM];   // [b][h][s][d]
__device__ float g_k[BATCH*NHEAD*SEQ*HDIM];
__device__ float g_v[BATCH*NHEAD*SEQ*HDIM];
__device__ float g_ctx[(size_t)MTOT*EMB];     // [b*s][e]

// ===========================================================================
// m16n8k16 fp16 mma.sync, fp32 accumulate. Calibrated R5-R13: sm_103 legacy
// HMMA runs at ~0.174 warp-mma/cyc/SM regardless of occupancy/buffering.
// QKV is at its 3-pass mma floor (343us); flash's slack is its serial fill.
// ===========================================================================
__device__ __forceinline__ void mma16(float* d, const uint32_t* a, const uint32_t* b) {
    asm volatile(
        "mma.sync.aligned.m16n8k16.row.col.f32.f16.f16.f32 "
        "{%0,%1,%2,%3}, {%4,%5,%6,%7}, {%8,%9}, {%0,%1,%2,%3};"
        : "+f"(d[0]), "+f"(d[1]), "+f"(d[2]), "+f"(d[3])
        : "r"(a[0]), "r"(a[1]), "r"(a[2]), "r"(a[3]), "r"(b[0]), "r"(b[1]));
}

// Split float4 into fp16 (hi, lo) pair-packed b32 words.
__device__ __forceinline__ uint4 split4(float4 g) {
    __half2 h01 = __floats2half2_rn(g.x, g.y);
    __half2 h23 = __floats2half2_rn(g.z, g.w);
    float2 f01 = __half22float2(h01);
    float2 f23 = __half22float2(h23);
    __half2 l01 = __floats2half2_rn(g.x - f01.x, g.y - f01.y);
    __half2 l23 = __floats2half2_rn(g.z - f23.x, g.w - f23.y);
    uint4 r;
    r.x = *reinterpret_cast<uint32_t*>(&h01);
    r.y = *reinterpret_cast<uint32_t*>(&l01);
    r.z = *reinterpret_cast<uint32_t*>(&h23);
    r.w = *reinterpret_cast<uint32_t*>(&l23);
    return r;
}

// Pack two fp32 into fp16 hi-pair + lo-pair b32 words (register-only).
__device__ __forceinline__ void pack_hl(float x, float y, uint32_t& h, uint32_t& l) {
    __half2 hh = __floats2half2_rn(x, y);
    float2 f = __half22float2(hh);
    __half2 ll = __floats2half2_rn(x - f.x, y - f.y);
    h = *reinterpret_cast<uint32_t*>(&hh);
    l = *reinterpret_cast<uint32_t*>(&ll);
}

// ===========================================================================
// FP16 mma.sync GEMM (R13 winner, unchanged): 128x128 CTA, BK=32, 512 thr.
//   - QKV (EPI==0): Q/K tiles 3-pass (mandatory); V tiles 2-pass.
//   - proj (EPI==1): 1-pass.
// ===========================================================================
#define GEMM_STAGE_BYTES 32768
#define GEMM_SMEM_BYTES  (2*GEMM_STAGE_BYTES)   // 64 KB

template<int EPI>
__global__ __launch_bounds__(512) void mma_gemm_kernel(
    const float* __restrict__ Ain,
    const float* __restrict__ W,
    const float* __restrict__ bias,
    float* __restrict__ out,
    int K, int Nfull)
{
    extern __shared__ char dsmem[];
    const float* A = (EPI == 1) ? (const float*)g_ctx : Ain;

    const int tid  = threadIdx.x;
    const int wid  = tid >> 5;
    const int lane = tid & 31;
    const int wm   = wid & 3;
    const int wn   = wid >> 2;
    const int gr   = lane >> 2;
    const int tg   = lane & 3;
    const int m0   = blockIdx.y * 128;
    const int n0   = blockIdx.x * 128;

    const bool pass2 = (EPI == 0);                            // proj: 1-pass
    const bool pass3 = (EPI == 0) && ((n0 >> 10) != 2);       // Q/K: 3-pass

    const float *pA[2], *pB[2];
    int offA[2], offB[2];
    #pragma unroll
    for (int t = 0; t < 2; t++) {
        int idx = tid + t * 512;
        int row = idx >> 3;
        int c4  = idx & 7;
        pA[t] = A + (size_t)(m0 + row) * K + c4 * 4;
        pB[t] = W + (size_t)(n0 + row) * K + c4 * 4;
        int kk  = c4 >> 2;
        int kw4 = c4 & 3;
        int aih = kw4 >> 1;
        int tg0 = (kw4 & 1) * 2;
        int mt = row >> 4, rw = row & 15;
        int ai = (rw >> 3) | (aih << 1);
        offA[t] = (((kk*8 + mt)*4 + ai) << 5) + (rw & 7)*4 + tg0;
        int nt = row >> 3;
        offB[t] = (((kk*16 + nt)*2 + aih) << 5) + (row & 7)*4 + tg0;
    }

    float acc[2][4][4];
    #pragma unroll
    for (int i = 0; i < 2; i++)
        #pragma unroll
        for (int j = 0; j < 4; j++)
            #pragma unroll
            for (int v = 0; v < 4; v++) acc[i][j][v] = 0.f;

    float4 gA[2], gB[2];
    #pragma unroll
    for (int t = 0; t < 2; t++) {
        gA[t] = *(const float4*)(pA[t]);
        gB[t] = *(const float4*)(pB[t]);
    }
    {
        uint2* sA0 = (uint2*)(dsmem);
        uint2* sB0 = (uint2*)(dsmem + 16384);
        #pragma unroll
        for (int t = 0; t < 2; t++) {
            *(uint4*)(sA0 + offA[t]) = split4(gA[t]);
            *(uint4*)(sB0 + offB[t]) = split4(gB[t]);
        }
    }
    __syncthreads();

    const int niter = K >> 5;
    for (int it = 0; it < niter; it++) {
        const int p = it & 1;
        uint2* cA = (uint2*)(dsmem + p*GEMM_STAGE_BYTES);
        uint2* cB = (uint2*)(dsmem + p*GEMM_STAGE_BYTES + 16384);
        const bool more = (it + 1 < niter);

        if (more) {
            const int ko = (it + 1) << 5;
            #pragma unroll
            for (int t = 0; t < 2; t++) {
                gA[t] = *(const float4*)(pA[t] + ko);
                gB[t] = *(const float4*)(pB[t] + ko);
            }
        }

        #pragma unroll
        for (int kk = 0; kk < 2; kk++) {
            uint32_t ah[2][4], al[2][4], bh[4][2], bl[4][2];
            #pragma unroll
            for (int mt4 = 0; mt4 < 2; mt4++) {
                int mt = wm*2 + mt4;
                #pragma unroll
                for (int ai = 0; ai < 4; ai++) {
                    uint2 v = cA[(((kk*8 + mt)*4 + ai) << 5) + lane];
                    ah[mt4][ai] = v.x;
                    al[mt4][ai] = v.y;
                }
            }
            #pragma unroll
            for (int nt4 = 0; nt4 < 4; nt4++) {
                int nt = wn*4 + nt4;
                #pragma unroll
                for (int bi = 0; bi < 2; bi++) {
                    uint2 v = cB[(((kk*16 + nt)*2 + bi) << 5) + lane];
                    bh[nt4][bi] = v.x;
                    bl[nt4][bi] = v.y;
                }
            }
            #pragma unroll
            for (int mt4 = 0; mt4 < 2; mt4++)
                #pragma unroll
                for (int nt4 = 0; nt4 < 4; nt4++)
                    mma16(acc[mt4][nt4], ah[mt4], bh[nt4]);
            if (pass2) {
                #pragma unroll
                for (int mt4 = 0; mt4 < 2; mt4++)
                    #pragma unroll
                    for (int nt4 = 0; nt4 < 4; nt4++)
                        mma16(acc[mt4][nt4], ah[mt4], bl[nt4]);
            }
            if (pass3) {
                #pragma unroll
                for (int mt4 = 0; mt4 < 2; mt4++)
                    #pragma unroll
                    for (int nt4 = 0; nt4 < 4; nt4++)
                        mma16(acc[mt4][nt4], al[mt4], bh[nt4]);
            }
        }

        if (more) {
            uint2* nA = (uint2*)(dsmem + (p^1)*GEMM_STAGE_BYTES);
            uint2* nB = (uint2*)(dsmem + (p^1)*GEMM_STAGE_BYTES + 16384);
            #pragma unroll
            for (int t = 0; t < 2; t++) {
                *(uint4*)(nA + offA[t]) = split4(gA[t]);
                *(uint4*)(nB + offB[t]) = split4(gB[t]);
            }
        }
        __syncthreads();
    }

    #pragma unroll
    for (int mt4 = 0; mt4 < 2; mt4++) {
        const int mlo = m0 + wm*32 + mt4*16 + gr;
        const int mhi = mlo + 8;
        #pragma unroll
        for (int nt4 = 0; nt4 < 4; nt4++) {
            const int nn = n0 + wn*32 + nt4*8 + tg*2;
            const float* d = acc[mt4][nt4];
            if (EPI == 0) {
                const int which = n0 >> 10;
                float* dst = (which == 0) ? g_q : ((which == 1) ? g_k : g_v);
                const int nl = nn & 1023;
                const int h  = nl >> 6;
                const int dd = nl & (HDIM - 1);
                {
                    int b = mlo >> 11, s = mlo & (SEQ - 1);
                    *(float2*)&dst[(((b*NHEAD + h)*SEQ) + s)*HDIM + dd] =
                        make_float2(d[0], d[1]);
                }
                {
                    int b = mhi >> 11, s = mhi & (SEQ - 1);
                    *(float2*)&dst[(((b*NHEAD + h)*SEQ) + s)*HDIM + dd] =
                        make_float2(d[2], d[3]);
                }
            } else {
                float2 bv = *(const float2*)&bias[nn];
                *(float2*)&out[(size_t)mlo * Nfull + nn] =
                    make_float2(d[0] + bv.x, d[1] + bv.y);
                *(float2*)&out[(size_t)mhi * Nfull + nn] =
                    make_float2(d[2] + bv.x, d[3] + bv.y);
            }
        }
    }
}

// ===========================================================================
// Causal flash attention on tensor cores. R14 changes (numerics identical):
//   - Q fragments hoisted to REGISTERS (warp's 16 rows fixed): sQ deleted,
//     16 LDS.64/warp/tile removed, x8 scale + split done once from gmem.
//   - K/V smem DOUBLE-BUFFERED (2 x 24KB): LDG next tile -> mma current ->
//     split/STS next -> one sync. Fill overlaps mma instead of a serial
//     phase (R13 profile slack ~85us was the exposed fill).
// 3-pass S, 1-pass PV, LPT order unchanged.
// ===========================================================================
#define FLASH_STAGE_BYTES 24576               // K 16KB + V 8KB
#define FLASH_SMEM_BYTES  (2*FLASH_STAGE_BYTES)   // 48 KB

__global__ __launch_bounds__(256) void flash_mma_kernel()
{
    extern __shared__ char fsm[];

    const int qt = (gridDim.x - 1) - blockIdx.x;   // LPT: heavy blocks first
    const int h  = blockIdx.y;
    const int b  = blockIdx.z;
    const int bh = b*NHEAD + h;
    const float* Qg = g_q + (size_t)bh * SEQ * HDIM;
    const float* Kg = g_k + (size_t)bh * SEQ * HDIM;
    const float* Vg = g_v + (size_t)bh * SEQ * HDIM;

    const int tid  = threadIdx.x;
    const int w    = tid >> 5;
    const int lane = tid & 31;
    const int gr   = lane >> 2;
    const int tg   = lane & 3;
    const int q0   = qt * 128;

    // ---- Q fragments straight into registers (x8 scale folded) ----
    // A-frag (kk, ai): row = 16w + gr + (ai&1)*8, d = kk*16 + (ai>>1)*8 + tg*2
    uint32_t qfh[4][4], qfl[4][4];
    #pragma unroll
    for (int kk = 0; kk < 4; kk++)
        #pragma unroll
        for (int ai = 0; ai < 4; ai++) {
            int row = q0 + 16*w + gr + (ai & 1)*8;
            int d   = kk*16 + (ai >> 1)*8 + tg*2;
            float2 qv = *(const float2*)(Qg + (size_t)row*HDIM + d);
            pack_hl(qv.x*8.f, qv.y*8.f, qfh[kk][ai], qfl[kk][ai]);
        }

    // ---- per-thread fill slots (fixed offsets within a stage) ----
    // K: 4 float4/thread; V: 2x(2 float4)/thread with key-pair transpose.
    const float *pK[4], *pV0[2], *pV1[2];
    int offK[4], offV[2][4];
    #pragma unroll
    for (int t = 0; t < 4; t++) {
        int idx = tid + t * 256;   // 0..1023
        int row = idx >> 4;        // key 0..63
        int c4  = idx & 15;
        pK[t] = Kg + (size_t)row*HDIM + c4*4;
        int kk  = c4 >> 2;
        int kw4 = c4 & 3;
        int bi  = kw4 >> 1;
        int tg0 = (kw4 & 1) * 2;
        int nt  = row >> 3;
        offK[t] = (((kk*8 + nt)*2 + bi) << 5) + (row & 7)*4 + tg0;  // uint2 idx
    }
    #pragma unroll
    for (int t = 0; t < 2; t++) {
        int idx = tid + t * 256;   // 0..511
        int kp  = idx >> 4;        // key pair 0..31
        int c4  = idx & 15;        // d/4
        pV0[t] = Vg + (size_t)(2*kp    )*HDIM + c4*4;
        pV1[t] = Vg + (size_t)(2*kp + 1)*HDIM + c4*4;
        int kkv = kp >> 3;
        int tgp = kp & 7;
        int bi  = tgp >> 2;
        int tgv = tgp & 3;
        #pragma unroll
        for (int j = 0; j < 4; j++) {
            int d   = c4*4 + j;
            int nt  = d >> 3;
            int grv = d & 7;
            int ln  = (grv*4 + tgv) ^ ((nt & 3) << 2);   // bank swizzle
            offV[t][j] = (((kkv*8 + nt)*2 + bi) << 5) + ln;  // uint32 idx
        }
    }

    float m0 = -1e30f, m1 = -1e30f, l0 = 0.f, l1 = 0.f;
    float cacc[8][4];
    #pragma unroll
    for (int nt = 0; nt < 8; nt++)
        #pragma unroll
        for (int v = 0; v < 4; v++) cacc[nt][v] = 0.f;

    const int qrow0 = q0 + 16*w + gr;   // thread's low row
    const int nkt   = 2*qt + 2;         // causal kv-tile count

    // ---- prologue: load + fill stage 0 ----
    float4 gK[4], gVa[2], gVb[2];
    #pragma unroll
    for (int t = 0; t < 4; t++) gK[t]  = *(const float4*)(pK[t]);
    #pragma unroll
    for (int t = 0; t < 2; t++) {
        gVa[t] = *(const float4*)(pV0[t]);
        gVb[t] = *(const float4*)(pV1[t]);
    }
    {
        uint2*    sK0 = (uint2*)(fsm);
        uint32_t* sV0 = (uint32_t*)(fsm + 16384);
        #pragma unroll
        for (int t = 0; t < 4; t++) *(uint4*)(sK0 + offK[t]) = split4(gK[t]);
        #pragma unroll
        for (int t = 0; t < 2; t++) {
            const float a0[4] = {gVa[t].x, gVa[t].y, gVa[t].z, gVa[t].w};
            const float a1[4] = {gVb[t].x, gVb[t].y, gVb[t].z, gVb[t].w};
            #pragma unroll
            for (int j = 0; j < 4; j++) {
                __half2 hh = __floats2half2_rn(a0[j], a1[j]);
                sV0[offV[t][j]] = *reinterpret_cast<uint32_t*>(&hh);
            }
        }
    }
    __syncthreads();

    for (int kt = 0; kt < nkt; kt++) {
        const int k0 = kt * 64;
        const int p  = kt & 1;
        uint2*    cK = (uint2*)(fsm + p*FLASH_STAGE_BYTES);
        uint32_t* cV = (uint32_t*)(fsm + p*FLASH_STAGE_BYTES + 16384);
        const bool more = (kt + 1 < nkt);

        // ---- prefetch next tile into registers (hidden under mma) ----
        if (more) {
            const int ko = (kt + 1) * 64 * HDIM;
            #pragma unroll
            for (int t = 0; t < 4; t++) gK[t]  = *(const float4*)(pK[t] + ko);
            #pragma unroll
            for (int t = 0; t < 2; t++) {
                gVa[t] = *(const float4*)(pV0[t] + ko);
                gVb[t] = *(const float4*)(pV1[t] + ko);
            }
        }

        // warps whose rows are entirely left of this kv tile: skip compute
        if (k0 <= q0 + 16*w + 15) {
            // ---- S = (16q) @ K^T via 3xFP16 (Q from registers) ----
            float sacc[8][4];
            #pragma unroll
            for (int nt = 0; nt < 8; nt++)
                #pragma unroll
                for (int v = 0; v < 4; v++) sacc[nt][v] = 0.f;

            #pragma unroll
            for (int kk = 0; kk < 4; kk++) {
                uint32_t kh[8][2], kl[8][2];
                #pragma unroll
                for (int nt = 0; nt < 8; nt++)
                    #pragma unroll
                    for (int bi = 0; bi < 2; bi++) {
                        uint2 v = cK[(((kk*8 + nt)*2 + bi) << 5) + lane];
                        kh[nt][bi] = v.x; kl[nt][bi] = v.y;
                    }
                #pragma unroll
                for (int nt = 0; nt < 8; nt++) mma16(sacc[nt], qfh[kk], kh[nt]);
                #pragma unroll
                for (int nt = 0; nt < 8; nt++) mma16(sacc[nt], qfh[kk], kl[nt]);
                #pragma unroll
                for (int nt = 0; nt < 8; nt++) mma16(sacc[nt], qfl[kk], kh[nt]);
            }

            // ---- causal mask (diagonal region only) ----
            if (k0 + 63 > qrow0 || k0 + 63 > qrow0 + 8) {
                #pragma unroll
                for (int nt = 0; nt < 8; nt++) {
                    int c = k0 + nt*8 + 2*tg;
                    if (c     > qrow0    ) sacc[nt][0] = -1e30f;
                    if (c + 1 > qrow0    ) sacc[nt][1] = -1e30f;
                    if (c     > qrow0 + 8) sacc[nt][2] = -1e30f;
                    if (c + 1 > qrow0 + 8) sacc[nt][3] = -1e30f;
                }
            }

            // ---- online softmax (rows gr, gr+8; reduce over 4 tg lanes) ----
            float mx0 = -1e30f, mx1 = -1e30f;
            #pragma unroll
            for (int nt = 0; nt < 8; nt++) {
                mx0 = fmaxf(mx0, fmaxf(sacc[nt][0], sacc[nt][1]));
                mx1 = fmaxf(mx1, fmaxf(sacc[nt][2], sacc[nt][3]));
            }
            mx0 = fmaxf(mx0, __shfl_xor_sync(0xffffffffu, mx0, 1));
            mx0 = fmaxf(mx0, __shfl_xor_sync(0xffffffffu, mx0, 2));
            mx1 = fmaxf(mx1, __shfl_xor_sync(0xffffffffu, mx1, 1));
            mx1 = fmaxf(mx1, __shfl_xor_sync(0xffffffffu, mx1, 2));
            float mn0 = fmaxf(m0, mx0), mn1 = fmaxf(m1, mx1);
            float al0 = __expf(m0 - mn0), al1 = __expf(m1 - mn1);
            m0 = mn0; m1 = mn1;

            float rs0 = 0.f, rs1 = 0.f;
            #pragma unroll
            for (int nt = 0; nt < 8; nt++) {
                sacc[nt][0] = __expf(sacc[nt][0] - mn0); rs0 += sacc[nt][0];
                sacc[nt][1] = __expf(sacc[nt][1] - mn0); rs0 += sacc[nt][1];
                sacc[nt][2] = __expf(sacc[nt][2] - mn1); rs1 += sacc[nt][2];
                sacc[nt][3] = __expf(sacc[nt][3] - mn1); rs1 += sacc[nt][3];
            }
            rs0 += __shfl_xor_sync(0xffffffffu, rs0, 1);
            rs0 += __shfl_xor_sync(0xffffffffu, rs0, 2);
            rs1 += __shfl_xor_sync(0xffffffffu, rs1, 1);
            rs1 += __shfl_xor_sync(0xffffffffu, rs1, 2);
            l0 = l0 * al0 + rs0;
            l1 = l1 * al1 + rs1;

            #pragma unroll
            for (int nt = 0; nt < 8; nt++) {
                cacc[nt][0] *= al0; cacc[nt][1] *= al0;
                cacc[nt][2] *= al1; cacc[nt][3] *= al1;
            }

            // ---- PV (1-pass): P hi from registers x V hi ----
            #pragma unroll
            for (int kkv = 0; kkv < 4; kkv++) {
                uint32_t ph[4], vh[8][2];
                {
                    __half2 h0 = __floats2half2_rn(sacc[2*kkv  ][0], sacc[2*kkv  ][1]);
                    __half2 h1 = __floats2half2_rn(sacc[2*kkv  ][2], sacc[2*kkv  ][3]);
                    __half2 h2 = __floats2half2_rn(sacc[2*kkv+1][0], sacc[2*kkv+1][1]);
                    __half2 h3 = __floats2half2_rn(sacc[2*kkv+1][2], sacc[2*kkv+1][3]);
                    ph[0] = *reinterpret_cast<uint32_t*>(&h0);
                    ph[1] = *reinterpret_cast<uint32_t*>(&h1);
                    ph[2] = *reinterpret_cast<uint32_t*>(&h2);
                    ph[3] = *reinterpret_cast<uint32_t*>(&h3);
                }
                #pragma unroll
                for (int nt = 0; nt < 8; nt++) {
                    int ln = lane ^ ((nt & 3) << 2);
                    #pragma unroll
                    for (int bi = 0; bi < 2; bi++)
                        vh[nt][bi] = cV[(((kkv*8 + nt)*2 + bi) << 5) + ln];
                }
                #pragma unroll
                for (int nt = 0; nt < 8; nt++) mma16(cacc[nt], ph, vh[nt]);
            }
        }

        // ---- fill the other stage (read by mma at kt+1) ----
        if (more) {
            uint2*    nK = (uint2*)(fsm + (p^1)*FLASH_STAGE_BYTES);
            uint32_t* nV = (uint32_t*)(fsm + (p^1)*FLASH_STAGE_BYTES + 16384);
            #pragma unroll
            for (int t = 0; t < 4; t++) *(uint4*)(nK + offK[t]) = split4(gK[t]);
            #pragma unroll
            for (int t = 0; t < 2; t++) {
                const float a0[4] = {gVa[t].x, gVa[t].y, gVa[t].z, gVa[t].w};
                const float a1[4] = {gVb[t].x, gVb[t].y, gVb[t].z, gVb[t].w};
                #pragma unroll
                for (int j = 0; j < 4; j++) {
                    __half2 hh = __floats2half2_rn(a0[j], a1[j]);
                    nV[offV[t][j]] = *reinterpret_cast<uint32_t*>(&hh);
                }
            }
        }
        __syncthreads();
    }

    // ---- epilogue: ctx[b][s][h*64+d] = acc / l ----
    const float inv0 = 1.0f / l0;
    const float inv1 = 1.0f / l1;
    float* o0 = g_ctx + ((size_t)(b*SEQ + qrow0    )) * EMB + h*HDIM;
    float* o1 = g_ctx + ((size_t)(b*SEQ + qrow0 + 8)) * EMB + h*HDIM;
    #pragma unroll
    for (int nt = 0; nt < 8; nt++) {
        int d = nt*8 + 2*tg;
        *(float2*)(o0 + d) = make_float2(cacc[nt][0]*inv0, cacc[nt][1]*inv0);
        *(float2*)(o1 + d) = make_float2(cacc[nt][2]*inv1, cacc[nt][3]*inv1);
    }
}

// ---------------------------------------------------------------------------
// Inputs (metadata order): x [2,2048,1024] f32, w_qkv [3072,1024] f32,
// w_proj [1024,1024] f32, b_proj [1024] f32. Output: [2,2048,1024] f32.
// ---------------------------------------------------------------------------
extern "C" void kernel_launch(void* const* d_in, const int* in_sizes, int n_in,
                              void* d_out, int out_size)
{
    (void)in_sizes; (void)n_in; (void)out_size;
    const float* x      = (const float*)d_in[0];
    const float* w_qkv  = (const float*)d_in[1];
    const float* w_proj = (const float*)d_in[2];
    const float* b_proj = (const float*)d_in[3];
    float* out = (float*)d_out;

    cudaFuncSetAttribute(mma_gemm_kernel<0>,
                         cudaFuncAttributeMaxDynamicSharedMemorySize, GEMM_SMEM_BYTES);
    cudaFuncSetAttribute(mma_gemm_kernel<1>,
                         cudaFuncAttributeMaxDynamicSharedMemorySize, GEMM_SMEM_BYTES);
    cudaFuncSetAttribute(flash_mma_kernel,
                         cudaFuncAttributeMaxDynamicSharedMemorySize, FLASH_SMEM_BYTES);

    // 1) QKV GEMM (3-pass Q/K, 2-pass V): -> g_q/g_k/g_v
    dim3 g1((3*EMB)/128, MTOT/128);
    mma_gemm_kernel<0><<<g1, 512, GEMM_SMEM_BYTES>>>(x, w_qkv, nullptr, nullptr,
                                                     EMB, 3*EMB);

    // 2) Causal flash attention (reg-Q, double-buffered K/V) -> g_ctx
    dim3 g2(SEQ/128, NHEAD, BATCH);
    flash_mma_kernel<<<g2, 256, FLASH_SMEM_BYTES>>>();

    // 3) Proj GEMM + bias (1-pass): g_ctx @ w_proj^T + b_proj -> out
    dim3 g3(EMB/128, MTOT/128);
    mma_gemm_kernel<1><<<g3, 512, GEMM_SMEM_BYTES>>>(nullptr, w_proj, b_proj, out,
                                                     EMB, EMB);
}